// round 5
// baseline (speedup 1.0000x reference)
#include <cuda_runtime.h>
#include <cuda_bf16.h>
#include <math.h>

#define SEQ    2048
#define DMODEL 2048
#define NHEADS 16
#define DKH    128

// ------------------------- scratch (device globals) -------------------------
__device__ float g_q[SEQ * DMODEL];                      // [s, h*128+k]
__device__ float g_k[SEQ * DMODEL];
__device__ float g_v[SEQ * DMODEL];
__device__ float g_vT[NHEADS * DKH * SEQ];               // [h][n][t]
__device__ float g_scores[(size_t)NHEADS * SEQ * SEQ];   // [h][s][t]
__device__ float g_concat[SEQ * DMODEL];                 // [s, h*128+n]
__device__ float g_wqT[NHEADS * DKH * DMODEL];           // [h][n][d]
__device__ float g_wkT[NHEADS * DKH * DMODEL];
__device__ float g_wvT[NHEADS * DKH * DMODEL];
__device__ float g_woT[DMODEL * DMODEL];                 // [n][k]

// ------------------------- helpers -------------------------
__device__ __forceinline__ unsigned smem_u32(const void* p) {
    unsigned a;
    asm("{ .reg .u64 t; cvta.to.shared.u64 t, %1; cvt.u32.u64 %0, t; }" : "=r"(a) : "l"(p));
    return a;
}

// Custom swizzle for 64-byte rows (4 x 16B granules per row):
// granule-col index c is XORed with perm(row) = {row bit1 -> c bit1, row bit2 -> c bit0}.
// Conflict-free for BOTH the STS.128 store pattern (rows tid>>1, col pair) and
// the ldmatrix 8-row column reads.
__device__ __forceinline__ unsigned swz(unsigned o) {
    return o ^ ((((o >> 7) & 1u) << 5) | (((o >> 8) & 1u) << 4));
}

__device__ __forceinline__ void ldsm4(unsigned* r, unsigned addr) {
    asm volatile("ldmatrix.sync.aligned.m8n8.x4.shared.b16 {%0,%1,%2,%3}, [%4];"
        : "=r"(r[0]), "=r"(r[1]), "=r"(r[2]), "=r"(r[3]) : "r"(addr));
}

__device__ __forceinline__ void mma16816(float* d, const unsigned* a, unsigned b0, unsigned b1) {
    asm volatile("mma.sync.aligned.m16n8k16.row.col.f32.bf16.bf16.f32 "
        "{%0,%1,%2,%3}, {%4,%5,%6,%7}, {%8,%9}, {%0,%1,%2,%3};"
        : "+f"(d[0]), "+f"(d[1]), "+f"(d[2]), "+f"(d[3])
        : "r"(a[0]), "r"(a[1]), "r"(a[2]), "r"(a[3]), "r"(b0), "r"(b1));
}

// convert 8 fp32 -> 8 bf16 hi + 8 bf16 lo (residual), store 16B each
__device__ __forceinline__ void cvt_store(void* hid, void* lod, float4 x0, float4 x1) {
    float xs[8] = {x0.x, x0.y, x0.z, x0.w, x1.x, x1.y, x1.z, x1.w};
    unsigned hp[4], lp[4];
#pragma unroll
    for (int i = 0; i < 4; i++) {
        unsigned h;
        asm("cvt.rn.satfinite.bf16x2.f32 %0, %1, %2;" : "=r"(h) : "f"(xs[2*i+1]), "f"(xs[2*i]));
        float h0 = __uint_as_float(h << 16);
        float h1 = __uint_as_float(h & 0xFFFF0000u);
        float l0 = xs[2*i]   - h0;
        float l1 = xs[2*i+1] - h1;
        unsigned l;
        asm("cvt.rn.satfinite.bf16x2.f32 %0, %1, %2;" : "=r"(l) : "f"(l1), "f"(l0));
        hp[i] = h; lp[i] = l;
    }
    *(uint4*)hid = make_uint4(hp[0], hp[1], hp[2], hp[3]);
    *(uint4*)lod = make_uint4(lp[0], lp[1], lp[2], lp[3]);
}

// ------------------------- smem layout (static, 32 KB) -------------------------
#define OFF_AHI 0
#define OFF_ALO 8192
#define OFF_BHI 16384
#define OFF_BLO 24576

// ------------------------- warp-MMA GEMM -------------------------
// C[z][m,n] = scale * sum_k A[z][m,k]*B[z][n,k]  (+ bias[z][n])
// A: [M,K] k-contiguous, row stride lda. B: [N,K] k-contiguous, row stride ldb.
// Tiles: M=128 (blockIdx.y), N=128 (blockIdx.x). K multiple of 32. 256 threads.
__global__ void __launch_bounds__(256, 1)
mma_gemm(const float* __restrict__ A, const float* __restrict__ B,
         const float* __restrict__ bias, float* __restrict__ C,
         int K, int lda, long abatch, int ldb, long bbatch,
         int ldc, long cbatch, long biasbatch, float scale, int has_bias)
{
    __shared__ __align__(1024) char sm[32768];
    const unsigned sb = smem_u32(sm);
    const int tid  = threadIdx.x;
    const int lane = tid & 31;
    const int wid  = tid >> 5;
    const int wm   = wid & 3;        // warp row tile: 4 x 32 = 128 M
    const int wn   = wid >> 2;       // warp col tile: 2 x 64 = 128 N
    const int z    = blockIdx.z;

    A += (long)z * abatch + (long)blockIdx.y * 128 * lda;
    B += (long)z * bbatch + (long)blockIdx.x * 128 * ldb;
    C += (long)z * cbatch + (long)blockIdx.y * 128 * ldc + (long)blockIdx.x * 128;

    float acc[2][8][4];
#pragma unroll
    for (int mt = 0; mt < 2; mt++)
#pragma unroll
        for (int nt = 0; nt < 8; nt++)
#pragma unroll
            for (int i = 0; i < 4; i++) acc[mt][nt][i] = 0.0f;

    // staging coords: each thread loads 16 floats of one row (k half)
    const int lrow = tid >> 1;            // 0..127
    const int lk   = (tid & 1) * 16;      // float offset 0 or 16
    const unsigned so1 = swz((unsigned)(lrow * 64 + lk * 2));
    const unsigned so2 = swz((unsigned)(lrow * 64 + lk * 2 + 16));

    // ldmatrix coords
    const int arow = wm * 32 + (lane & 15);
    const int brow = wn * 64 + (lane & 15);
    const unsigned hi16 = (unsigned)((lane >> 4) * 16);

    const int nch = K >> 5;
    float4 pa[4], pb[4];
    {
        const float* Ap = A + (long)lrow * lda + lk;
        const float* Bp = B + (long)lrow * ldb + lk;
#pragma unroll
        for (int i = 0; i < 4; i++) { pa[i] = *(const float4*)(Ap + 4*i); pb[i] = *(const float4*)(Bp + 4*i); }
    }

    for (int ch = 0; ch < nch; ch++) {
        cvt_store(sm + OFF_AHI + so1, sm + OFF_ALO + so1, pa[0], pa[1]);
        cvt_store(sm + OFF_AHI + so2, sm + OFF_ALO + so2, pa[2], pa[3]);
        cvt_store(sm + OFF_BHI + so1, sm + OFF_BLO + so1, pb[0], pb[1]);
        cvt_store(sm + OFF_BHI + so2, sm + OFF_BLO + so2, pb[2], pb[3]);
        __syncthreads();

        if (ch + 1 < nch) {  // prefetch next chunk into registers (overlaps MMA)
            const float* Ap = A + (ch + 1) * 32 + (long)lrow * lda + lk;
            const float* Bp = B + (ch + 1) * 32 + (long)lrow * ldb + lk;
#pragma unroll
            for (int i = 0; i < 4; i++) { pa[i] = *(const float4*)(Ap + 4*i); pb[i] = *(const float4*)(Bp + 4*i); }
        }

#pragma unroll
        for (int k16 = 0; k16 < 2; k16++) {
            const unsigned kb = (unsigned)(k16 * 32) + hi16;
            unsigned ahi[2][4], alo[2][4];
#pragma unroll
            for (int mt = 0; mt < 2; mt++) {
                const unsigned off = swz((unsigned)((arow + mt * 16) * 64) + kb);
                ldsm4(ahi[mt], sb + OFF_AHI + off);
                ldsm4(alo[mt], sb + OFF_ALO + off);
            }
#pragma unroll
            for (int g = 0; g < 4; g++) {
                const unsigned off = swz((unsigned)((brow + g * 16) * 64) + kb);
                unsigned bh[4], bl[4];
                ldsm4(bh, sb + OFF_BHI + off);
                ldsm4(bl, sb + OFF_BLO + off);
#pragma unroll
                for (int mt = 0; mt < 2; mt++) {
                    mma16816(acc[mt][2*g],   ahi[mt], bh[0], bh[2]);   // hi*hi
                    mma16816(acc[mt][2*g+1], ahi[mt], bh[1], bh[3]);
                    mma16816(acc[mt][2*g],   ahi[mt], bl[0], bl[2]);   // hi*lo
                    mma16816(acc[mt][2*g+1], ahi[mt], bl[1], bl[3]);
                    mma16816(acc[mt][2*g],   alo[mt], bh[0], bh[2]);   // lo*hi
                    mma16816(acc[mt][2*g+1], alo[mt], bh[1], bh[3]);
                }
            }
        }
        __syncthreads();
    }

    // ---------------- epilogue: direct register -> gmem ----------------
    const float* bz = has_bias ? (bias + (long)z * biasbatch + (long)blockIdx.x * 128) : nullptr;
#pragma unroll
    for (int mt = 0; mt < 2; mt++) {
        const int row = wm * 32 + mt * 16 + (lane >> 2);
#pragma unroll
        for (int nt = 0; nt < 8; nt++) {
            const int col = wn * 64 + nt * 8 + (lane & 3) * 2;
            float2 v01, v23;
            v01.x = acc[mt][nt][0] * scale; v01.y = acc[mt][nt][1] * scale;
            v23.x = acc[mt][nt][2] * scale; v23.y = acc[mt][nt][3] * scale;
            if (bz) {
                const float b0 = bz[col], b1 = bz[col + 1];
                v01.x += b0; v01.y += b1; v23.x += b0; v23.y += b1;
            }
            *(float2*)(C + (long)row * ldc + col)       = v01;
            *(float2*)(C + (long)(row + 8) * ldc + col) = v23;
        }
    }
}

// ------------------------- batched tiled transpose -------------------------
// out[z][c][r] = in[z][r][c], c contiguous on input, r contiguous on output.
__global__ __launch_bounds__(256)
void transpose_kernel(const float* __restrict__ in, float* __restrict__ out,
                      long ibatch, int istride, long obatch, int ostride)
{
    __shared__ float tile[32][33];
    const int z = blockIdx.z;
    in += (long)z * ibatch;
    out += (long)z * obatch;
    const int c0 = blockIdx.x * 32;
    const int r0 = blockIdx.y * 32;
    const int tx = threadIdx.x & 31;
    const int ty = threadIdx.x >> 5;   // 0..7
#pragma unroll
    for (int j = 0; j < 4; j++)
        tile[ty + 8 * j][tx] = in[(long)(r0 + ty + 8 * j) * istride + c0 + tx];
    __syncthreads();
#pragma unroll
    for (int j = 0; j < 4; j++)
        out[(long)(c0 + ty + 8 * j) * ostride + r0 + tx] = tile[tx][ty + 8 * j];
}

// ------------------------- FMA-only exp (avoids MUFU bottleneck) -------------------------
__device__ __forceinline__ float fexp(float x) {
    float t = x * 1.4426950408889634f;
    t = fmaxf(t, -125.0f);
    const float k = rintf(t);
    const float f = t - k;
    float p = 1.3333558146e-3f;
    p = fmaf(p, f, 9.6181291076e-3f);
    p = fmaf(p, f, 5.5504108664e-2f);
    p = fmaf(p, f, 2.4022650696e-1f);
    p = fmaf(p, f, 6.9314718056e-1f);
    p = fmaf(p, f, 1.0f);
    return p * __int_as_float(((int)k + 127) << 23);
}

// ------------------------- softmax over s (the query axis) -------------------------
// scores[h][s][t]; normalize over s for each (h, t). In place. Coalesced across t.
__global__ __launch_bounds__(128)
void colsoftmax_kernel(float* __restrict__ sc)
{
    const int h = blockIdx.y;
    const int t = blockIdx.x * 128 + threadIdx.x;
    float* base = sc + (size_t)h * SEQ * SEQ + t;

    float m0 = -1e30f, m1 = -1e30f, m2 = -1e30f, m3 = -1e30f;
    float s0 = 0.f, s1 = 0.f, s2 = 0.f, s3 = 0.f;
    for (int s = 0; s < SEQ; s += 4) {
        const float v0 = base[(size_t)(s + 0) * SEQ];
        const float v1 = base[(size_t)(s + 1) * SEQ];
        const float v2 = base[(size_t)(s + 2) * SEQ];
        const float v3 = base[(size_t)(s + 3) * SEQ];
        if (v0 > m0) { s0 = s0 * fexp(m0 - v0) + 1.f; m0 = v0; } else s0 += fexp(v0 - m0);
        if (v1 > m1) { s1 = s1 * fexp(m1 - v1) + 1.f; m1 = v1; } else s1 += fexp(v1 - m1);
        if (v2 > m2) { s2 = s2 * fexp(m2 - v2) + 1.f; m2 = v2; } else s2 += fexp(v2 - m2);
        if (v3 > m3) { s3 = s3 * fexp(m3 - v3) + 1.f; m3 = v3; } else s3 += fexp(v3 - m3);
    }
    const float m = fmaxf(fmaxf(m0, m1), fmaxf(m2, m3));
    const float ssum = s0 * fexp(m0 - m) + s1 * fexp(m1 - m) +
                       s2 * fexp(m2 - m) + s3 * fexp(m3 - m);
    const float inv = 1.0f / ssum;
#pragma unroll 4
    for (int s = 0; s < SEQ; s++) {
        const float v = base[(size_t)s * SEQ];
        base[(size_t)s * SEQ] = fexp(v - m) * inv;
    }
}

// ------------------------- launch -------------------------
extern "C" void kernel_launch(void* const* d_in, const int* in_sizes, int n_in,
                              void* d_out, int out_size)
{
    const float* query = (const float*)d_in[0];
    const float* key_  = (const float*)d_in[1];
    const float* value = (const float*)d_in[2];
    const float* Wq    = (const float*)d_in[3];
    const float* bq    = (const float*)d_in[4];
    const float* Wk    = (const float*)d_in[5];
    const float* bk    = (const float*)d_in[6];
    const float* Wv    = (const float*)d_in[7];
    const float* bv    = (const float*)d_in[8];
    const float* Wo    = (const float*)d_in[9];
    const float* bo    = (const float*)d_in[10];
    float* out = (float*)d_out;

    float *q, *k, *v, *vT, *sc, *cc, *wqT, *wkT, *wvT, *woT;
    cudaGetSymbolAddress((void**)&q,   g_q);
    cudaGetSymbolAddress((void**)&k,   g_k);
    cudaGetSymbolAddress((void**)&v,   g_v);
    cudaGetSymbolAddress((void**)&vT,  g_vT);
    cudaGetSymbolAddress((void**)&sc,  g_scores);
    cudaGetSymbolAddress((void**)&cc,  g_concat);
    cudaGetSymbolAddress((void**)&wqT, g_wqT);
    cudaGetSymbolAddress((void**)&wkT, g_wkT);
    cudaGetSymbolAddress((void**)&wvT, g_wvT);
    cudaGetSymbolAddress((void**)&woT, g_woT);

    const float inv_sqrt_dk = 0.088388347648318447f;  // 1/sqrt(128)

    // 0) transpose weights: Wx [h][d][n] -> WxT [h][n][d];  Wo [k][n] -> WoT [n][k]
    {
        dim3 g(DKH / 32, DMODEL / 32, NHEADS);
        transpose_kernel<<<g, 256>>>(Wq, wqT, (long)DMODEL * DKH, DKH, (long)DKH * DMODEL, DMODEL);
        transpose_kernel<<<g, 256>>>(Wk, wkT, (long)DMODEL * DKH, DKH, (long)DKH * DMODEL, DMODEL);
        transpose_kernel<<<g, 256>>>(Wv, wvT, (long)DMODEL * DKH, DKH, (long)DKH * DMODEL, DMODEL);
        dim3 go(DMODEL / 32, DMODEL / 32, 1);
        transpose_kernel<<<go, 256>>>(Wo, woT, 0, DMODEL, 0, DMODEL);
    }

    // 1) projections: q[s, h*128+n] = query @ Wq[h] + bq[h]
    {
        dim3 g(1, SEQ / 128, NHEADS);
        mma_gemm<<<g, 256>>>(query, wqT, bq, q, DMODEL,
                             DMODEL, 0L, DMODEL, (long)DKH * DMODEL,
                             DMODEL, (long)DKH, (long)DKH, 1.0f, 1);
        mma_gemm<<<g, 256>>>(key_, wkT, bk, k, DMODEL,
                             DMODEL, 0L, DMODEL, (long)DKH * DMODEL,
                             DMODEL, (long)DKH, (long)DKH, 1.0f, 1);
        mma_gemm<<<g, 256>>>(value, wvT, bv, v, DMODEL,
                             DMODEL, 0L, DMODEL, (long)DKH * DMODEL,
                             DMODEL, (long)DKH, (long)DKH, 1.0f, 1);
    }

    // 2) vT[h][n][t] = v[t][h*128+n]
    {
        dim3 g(DKH / 32, SEQ / 32, NHEADS);
        transpose_kernel<<<g, 256>>>(v, vT, (long)DKH, DMODEL, (long)DKH * SEQ, SEQ);
    }

    // 3) scores[h][s][t] = q_h[s,:] . k_h[t,:] / sqrt(dk)
    {
        dim3 g(SEQ / 128, SEQ / 128, NHEADS);
        mma_gemm<<<g, 256>>>(q, k, nullptr, sc, DKH,
                             DMODEL, (long)DKH, DMODEL, (long)DKH,
                             SEQ, (long)SEQ * SEQ, 0L, inv_sqrt_dk, 0);
    }

    // 4) softmax over the query axis s (per (h, t) column)
    {
        dim3 g(SEQ / 128, NHEADS);
        colsoftmax_kernel<<<g, 128>>>(sc);
    }

    // 5) concat[s, h*128+n] = sum_t attn[h][s][t] * vT[h][n][t]
    {
        dim3 g(1, SEQ / 128, NHEADS);
        mma_gemm<<<g, 256>>>(sc, vT, nullptr, cc, SEQ,
                             SEQ, (long)SEQ * SEQ, SEQ, (long)DKH * SEQ,
                             DMODEL, (long)DKH, 0L, 1.0f, 0);
    }

    // 6) out = concat @ Wo + bo
    {
        dim3 g(DMODEL / 128, SEQ / 128, 1);
        mma_gemm<<<g, 256>>>(cc, woT, bo, out, DMODEL,
                             DMODEL, 0L, DMODEL, 0L,
                             DMODEL, 0L, 0L, 1.0f, 1);
    }
}

// round 7
// speedup vs baseline: 1.0086x; 1.0086x over previous
#include <cuda_runtime.h>
#include <cuda_bf16.h>
#include <math.h>

#define SEQ    2048
#define DMODEL 2048
#define NHEADS 16
#define DKH    128
typedef __nv_bfloat16 bf16;

// ------------------------- scratch (device globals) -------------------------
__device__ bf16 g_qryh[SEQ * DMODEL], g_qryl[SEQ * DMODEL];
__device__ bf16 g_keyh[SEQ * DMODEL], g_keyl[SEQ * DMODEL];
__device__ bf16 g_valh[SEQ * DMODEL], g_vall[SEQ * DMODEL];
__device__ bf16 g_wqTh[NHEADS * DKH * DMODEL], g_wqTl[NHEADS * DKH * DMODEL];
__device__ bf16 g_wkTh[NHEADS * DKH * DMODEL], g_wkTl[NHEADS * DKH * DMODEL];
__device__ bf16 g_wvTh[NHEADS * DKH * DMODEL], g_wvTl[NHEADS * DKH * DMODEL];
__device__ bf16 g_woTh[DMODEL * DMODEL], g_woTl[DMODEL * DMODEL];
__device__ bf16 g_qh[SEQ * DMODEL], g_ql[SEQ * DMODEL];
__device__ bf16 g_kh[SEQ * DMODEL], g_kl[SEQ * DMODEL];
__device__ float g_v[SEQ * DMODEL];
__device__ bf16 g_vTh[NHEADS * DKH * SEQ], g_vTl[NHEADS * DKH * SEQ];
__device__ float g_sc[(size_t)NHEADS * SEQ * SEQ];       // fp32 scores [h][s][t]
__device__ bf16 g_attnh[(size_t)NHEADS * SEQ * SEQ];     // bf16 attn hi [h][s][t]
__device__ bf16 g_attnl[(size_t)NHEADS * SEQ * SEQ];     // bf16 attn lo
__device__ bf16 g_cch[SEQ * DMODEL], g_ccl[SEQ * DMODEL];

// ------------------------- helpers -------------------------
__device__ __forceinline__ unsigned smem_u32(const void* p) {
    unsigned a;
    asm("{ .reg .u64 t; cvta.to.shared.u64 t, %1; cvt.u32.u64 %0, t; }" : "=r"(a) : "l"(p));
    return a;
}
// swizzle for 64-byte rows: conflict-free for STS/cp.async granules AND ldmatrix reads
__device__ __forceinline__ unsigned swz(unsigned o) {
    return o ^ ((((o >> 7) & 1u) << 5) | (((o >> 8) & 1u) << 4));
}
__device__ __forceinline__ void ldsm4(unsigned* r, unsigned addr) {
    asm volatile("ldmatrix.sync.aligned.m8n8.x4.shared.b16 {%0,%1,%2,%3}, [%4];"
        : "=r"(r[0]), "=r"(r[1]), "=r"(r[2]), "=r"(r[3]) : "r"(addr));
}
__device__ __forceinline__ void mma16816(float* d, const unsigned* a, unsigned b0, unsigned b1) {
    asm volatile("mma.sync.aligned.m16n8k16.row.col.f32.bf16.bf16.f32 "
        "{%0,%1,%2,%3}, {%4,%5,%6,%7}, {%8,%9}, {%0,%1,%2,%3};"
        : "+f"(d[0]), "+f"(d[1]), "+f"(d[2]), "+f"(d[3])
        : "r"(a[0]), "r"(a[1]), "r"(a[2]), "r"(a[3]), "r"(b0), "r"(b1));
}
__device__ __forceinline__ void cp16(unsigned dst, const void* src) {
    asm volatile("cp.async.cg.shared.global [%0], [%1], 16;" :: "r"(dst), "l"(src));
}
#define CP_COMMIT() asm volatile("cp.async.commit_group;" ::: "memory")
#define CP_WAIT(n)  asm volatile("cp.async.wait_group %0;" :: "n"(n) : "memory")

// split 8 fp32 into bf16 hi + lo residual planes (packed bf16x2 words)
__device__ __forceinline__ void cvt8(float4 x0, float4 x1, uint4* hp4, uint4* lp4) {
    float xs[8] = {x0.x, x0.y, x0.z, x0.w, x1.x, x1.y, x1.z, x1.w};
    unsigned hp[4], lp[4];
#pragma unroll
    for (int i = 0; i < 4; i++) {
        unsigned h;
        asm("cvt.rn.satfinite.bf16x2.f32 %0, %1, %2;" : "=r"(h) : "f"(xs[2*i+1]), "f"(xs[2*i]));
        float l0 = xs[2*i]   - __uint_as_float(h << 16);
        float l1 = xs[2*i+1] - __uint_as_float(h & 0xFFFF0000u);
        unsigned l;
        asm("cvt.rn.satfinite.bf16x2.f32 %0, %1, %2;" : "=r"(l) : "f"(l1), "f"(l0));
        hp[i] = h; lp[i] = l;
    }
    *hp4 = make_uint4(hp[0], hp[1], hp[2], hp[3]);
    *lp4 = make_uint4(lp[0], lp[1], lp[2], lp[3]);
}

// ------------------------- bf16 pipelined warp-MMA GEMM -------------------------
// C[z][m,n] = scale * sum_k A[z][m,k]*B[z][n,k] (+ bias[z][n])
// A/B bf16 hi(/lo) planes, k-contiguous. PASSES: 3 = hi.hi+hi.lo+lo.hi, 2 = a.bhi+a.blo
// EPI: 0 = fp32 C, 1 = bf16 hi/lo planes Chi/Clo.
#define ST_A_HI 0
#define ST_A_LO 8192
#define ST_B_HI 16384
#define ST_B_LO 24576
#define ST_STRIDE 32768
#define GSMEM 65536

template<int PASSES, int EPI>
__global__ void __launch_bounds__(256, 2)
mma_gemm(const bf16* __restrict__ Ahi, const bf16* __restrict__ Alo,
         const bf16* __restrict__ Bhi, const bf16* __restrict__ Blo,
         const float* __restrict__ bias, float* __restrict__ C,
         bf16* __restrict__ Chi, bf16* __restrict__ Clo,
         int K, int lda, long abatch, int ldb, long bbatch,
         int ldc, long cbatch, long biasbatch, float scale, int has_bias)
{
    extern __shared__ __align__(1024) char sm[];
    const unsigned sb = smem_u32(sm);
    const int tid  = threadIdx.x;
    const int lane = tid & 31;
    const int wid  = tid >> 5;
    const int wm   = wid & 3;
    const int wn   = wid >> 2;
    const int z    = blockIdx.z;

    Ahi += (long)z * abatch + (long)blockIdx.y * 128 * lda;
    Bhi += (long)z * bbatch + (long)blockIdx.x * 128 * ldb;
    if (PASSES == 3) {
        Alo += (long)z * abatch + (long)blockIdx.y * 128 * lda;
    }
    Blo += (long)z * bbatch + (long)blockIdx.x * 128 * ldb;

    float acc[2][8][4];
#pragma unroll
    for (int mt = 0; mt < 2; mt++)
#pragma unroll
        for (int nt = 0; nt < 8; nt++)
#pragma unroll
            for (int i = 0; i < 4; i++) acc[mt][nt][i] = 0.0f;

    // cp.async coords: row = tid>>1 (0..127), this thread covers granules gsel, gsel+1
    const int lrow = tid >> 1;
    const int gsel = (tid & 1) * 2;
    const unsigned d0 = swz((unsigned)(lrow * 64 + gsel * 16));
    const unsigned d1 = swz((unsigned)(lrow * 64 + gsel * 16 + 16));
    const long asrc = (long)lrow * lda + gsel * 8;
    const long bsrc = (long)lrow * ldb + gsel * 8;

    // ldmatrix coords
    const int arow = wm * 32 + (lane & 15);
    const int brow = wn * 64 + (lane & 15);
    const unsigned hi16 = (unsigned)((lane >> 4) * 16);

    const int nch = K >> 5;

#define LOAD_CHUNK(st, k0) do {                                                     \
    const unsigned b_ = sb + (st) * ST_STRIDE;                                      \
    cp16(b_ + ST_A_HI + d0, Ahi + asrc + (k0));                                     \
    cp16(b_ + ST_A_HI + d1, Ahi + asrc + (k0) + 8);                                 \
    if (PASSES == 3) {                                                              \
        cp16(b_ + ST_A_LO + d0, Alo + asrc + (k0));                                 \
        cp16(b_ + ST_A_LO + d1, Alo + asrc + (k0) + 8);                             \
    }                                                                               \
    cp16(b_ + ST_B_HI + d0, Bhi + bsrc + (k0));                                     \
    cp16(b_ + ST_B_HI + d1, Bhi + bsrc + (k0) + 8);                                 \
    cp16(b_ + ST_B_LO + d0, Blo + bsrc + (k0));                                     \
    cp16(b_ + ST_B_LO + d1, Blo + bsrc + (k0) + 8);                                 \
} while (0)

    LOAD_CHUNK(0, 0);
    CP_COMMIT();

    for (int ch = 0; ch < nch; ch++) {
        if (ch + 1 < nch) {
            LOAD_CHUNK((ch + 1) & 1, (ch + 1) * 32);
            CP_COMMIT();
            CP_WAIT(1);
        } else {
            CP_WAIT(0);
        }
        __syncthreads();

        const unsigned stb = sb + (ch & 1) * ST_STRIDE;
#pragma unroll
        for (int k16 = 0; k16 < 2; k16++) {
            const unsigned kb = (unsigned)(k16 * 32) + hi16;
            unsigned ahi[2][4], alo[2][4];
#pragma unroll
            for (int mt = 0; mt < 2; mt++) {
                const unsigned off = swz((unsigned)((arow + mt * 16) * 64) + kb);
                ldsm4(ahi[mt], stb + ST_A_HI + off);
                if (PASSES == 3) ldsm4(alo[mt], stb + ST_A_LO + off);
            }
#pragma unroll
            for (int g = 0; g < 4; g++) {
                const unsigned off = swz((unsigned)((brow + g * 16) * 64) + kb);
                unsigned bh[4], bl[4];
                ldsm4(bh, stb + ST_B_HI + off);
                ldsm4(bl, stb + ST_B_LO + off);
#pragma unroll
                for (int mt = 0; mt < 2; mt++) {
                    mma16816(acc[mt][2*g],   ahi[mt], bh[0], bh[2]);
                    mma16816(acc[mt][2*g+1], ahi[mt], bh[1], bh[3]);
                    mma16816(acc[mt][2*g],   ahi[mt], bl[0], bl[2]);
                    mma16816(acc[mt][2*g+1], ahi[mt], bl[1], bl[3]);
                    if (PASSES == 3) {
                        mma16816(acc[mt][2*g],   alo[mt], bh[0], bh[2]);
                        mma16816(acc[mt][2*g+1], alo[mt], bh[1], bh[3]);
                    }
                }
            }
        }
        __syncthreads();
    }
#undef LOAD_CHUNK

    // ---------------- epilogue ----------------
    const float* bz = bias + (long)z * biasbatch + (long)blockIdx.x * 128;
    if (EPI == 0) C += (long)z * cbatch + (long)blockIdx.y * 128 * ldc + (long)blockIdx.x * 128;
    else {
        Chi += (long)z * cbatch + (long)blockIdx.y * 128 * ldc + (long)blockIdx.x * 128;
        Clo += (long)z * cbatch + (long)blockIdx.y * 128 * ldc + (long)blockIdx.x * 128;
    }
#pragma unroll
    for (int mt = 0; mt < 2; mt++) {
        const int row = wm * 32 + mt * 16 + (lane >> 2);
#pragma unroll
        for (int nt = 0; nt < 8; nt++) {
            const int col = wn * 64 + nt * 8 + (lane & 3) * 2;
            float b0 = 0.f, b1 = 0.f;
            if (has_bias) { b0 = bz[col]; b1 = bz[col + 1]; }
            float x0 = fmaf(acc[mt][nt][0], scale, b0);
            float x1 = fmaf(acc[mt][nt][1], scale, b1);
            float x2 = fmaf(acc[mt][nt][2], scale, b0);
            float x3 = fmaf(acc[mt][nt][3], scale, b1);
            if (EPI == 0) {
                float2 v01; v01.x = x0; v01.y = x1;
                float2 v23; v23.x = x2; v23.y = x3;
                *(float2*)(C + (long)row * ldc + col)       = v01;
                *(float2*)(C + (long)(row + 8) * ldc + col) = v23;
            } else {
                unsigned h01, h23, l01, l23;
                asm("cvt.rn.satfinite.bf16x2.f32 %0, %1, %2;" : "=r"(h01) : "f"(x1), "f"(x0));
                asm("cvt.rn.satfinite.bf16x2.f32 %0, %1, %2;" : "=r"(h23) : "f"(x3), "f"(x2));
                float r0 = x0 - __uint_as_float(h01 << 16);
                float r1 = x1 - __uint_as_float(h01 & 0xFFFF0000u);
                float r2 = x2 - __uint_as_float(h23 << 16);
                float r3 = x3 - __uint_as_float(h23 & 0xFFFF0000u);
                asm("cvt.rn.satfinite.bf16x2.f32 %0, %1, %2;" : "=r"(l01) : "f"(r1), "f"(r0));
                asm("cvt.rn.satfinite.bf16x2.f32 %0, %1, %2;" : "=r"(l23) : "f"(r3), "f"(r2));
                *(unsigned*)(Chi + (long)row * ldc + col)       = h01;
                *(unsigned*)(Clo + (long)row * ldc + col)       = l01;
                *(unsigned*)(Chi + (long)(row + 8) * ldc + col) = h23;
                *(unsigned*)(Clo + (long)(row + 8) * ldc + col) = l23;
            }
        }
    }
}

// ------------------------- fp32 -> bf16 hi/lo planes (flat) -------------------------
__global__ void __launch_bounds__(256)
cvt_kernel(const float4* __restrict__ in, uint4* __restrict__ hi, uint4* __restrict__ lo, int n8)
{
    const int i = blockIdx.x * 256 + threadIdx.x;
    if (i >= n8) return;
    uint4 hp, lp;
    cvt8(in[2*i], in[2*i + 1], &hp, &lp);
    hi[i] = hp;
    lo[i] = lp;
}

// ------------------------- transpose + split: fp32 [r][c] -> bf16 hi/lo [c][r] -------------------------
__global__ void __launch_bounds__(256)
transpose_cvt_kernel(const float* __restrict__ in, bf16* __restrict__ oh, bf16* __restrict__ ol,
                     long ibatch, int istride, long obatch, int ostride)
{
    __shared__ float tile[32][33];
    const int z = blockIdx.z;
    in += (long)z * ibatch;
    oh += (long)z * obatch;
    ol += (long)z * obatch;
    const int c0 = blockIdx.x * 32;
    const int r0 = blockIdx.y * 32;
    const int tx = threadIdx.x & 31;
    const int ty = threadIdx.x >> 5;
#pragma unroll
    for (int j = 0; j < 4; j++)
        tile[ty + 8 * j][tx] = in[(long)(r0 + ty + 8 * j) * istride + c0 + tx];
    __syncthreads();
#pragma unroll
    for (int j = 0; j < 4; j++) {
        const float v = tile[tx][ty + 8 * j];
        const long o = (long)(c0 + ty + 8 * j) * ostride + r0 + tx;
        const bf16 h = __float2bfloat16(v);
        oh[o] = h;
        ol[o] = __float2bfloat16(v - __bfloat162float(h));
    }
}

// ------------------------- FMA-only exp -------------------------
__device__ __forceinline__ float fexp(float x) {
    float t = x * 1.4426950408889634f;
    t = fmaxf(t, -125.0f);
    const float k = rintf(t);
    const float f = t - k;
    float p = 1.3333558146e-3f;
    p = fmaf(p, f, 9.6181291076e-3f);
    p = fmaf(p, f, 5.5504108664e-2f);
    p = fmaf(p, f, 2.4022650696e-1f);
    p = fmaf(p, f, 6.9314718056e-1f);
    p = fmaf(p, f, 1.0f);
    return p * __int_as_float(((int)k + 127) << 23);
}

// ------------------------- softmax over s (query axis), fp32 in -> bf16 hi/lo out -------------------------
__global__ void __launch_bounds__(128)
colsoftmax_kernel(const float* __restrict__ sc, bf16* __restrict__ attnh, bf16* __restrict__ attnl)
{
    const int h = blockIdx.y;
    const int t = blockIdx.x * 128 + threadIdx.x;
    const float* base = sc + (size_t)h * SEQ * SEQ + t;
    bf16* ohase = attnh + (size_t)h * SEQ * SEQ + t;
    bf16* olase = attnl + (size_t)h * SEQ * SEQ + t;

    float m0 = -1e30f, m1 = -1e30f, m2 = -1e30f, m3 = -1e30f;
    float s0 = 0.f, s1 = 0.f, s2 = 0.f, s3 = 0.f;
    for (int s = 0; s < SEQ; s += 4) {
        const float v0 = base[(size_t)(s + 0) * SEQ];
        const float v1 = base[(size_t)(s + 1) * SEQ];
        const float v2 = base[(size_t)(s + 2) * SEQ];
        const float v3 = base[(size_t)(s + 3) * SEQ];
        if (v0 > m0) { s0 = s0 * fexp(m0 - v0) + 1.f; m0 = v0; } else s0 += fexp(v0 - m0);
        if (v1 > m1) { s1 = s1 * fexp(m1 - v1) + 1.f; m1 = v1; } else s1 += fexp(v1 - m1);
        if (v2 > m2) { s2 = s2 * fexp(m2 - v2) + 1.f; m2 = v2; } else s2 += fexp(v2 - m2);
        if (v3 > m3) { s3 = s3 * fexp(m3 - v3) + 1.f; m3 = v3; } else s3 += fexp(v3 - m3);
    }
    const float m = fmaxf(fmaxf(m0, m1), fmaxf(m2, m3));
    const float ssum = s0 * fexp(m0 - m) + s1 * fexp(m1 - m) +
                       s2 * fexp(m2 - m) + s3 * fexp(m3 - m);
    const float inv = 1.0f / ssum;
#pragma unroll 4
    for (int s = 0; s < SEQ; s++) {
        const float v = base[(size_t)s * SEQ];
        const float a = fexp(v - m) * inv;
        const bf16 ah = __float2bfloat16(a);
        ohase[(size_t)s * SEQ] = ah;
        olase[(size_t)s * SEQ] = __float2bfloat16(a - __bfloat162float(ah));
    }
}

// ------------------------- launch -------------------------
extern "C" void kernel_launch(void* const* d_in, const int* in_sizes, int n_in,
                              void* d_out, int out_size)
{
    const float* query = (const float*)d_in[0];
    const float* key_  = (const float*)d_in[1];
    const float* value = (const float*)d_in[2];
    const float* Wq    = (const float*)d_in[3];
    const float* bq    = (const float*)d_in[4];
    const float* Wk    = (const float*)d_in[5];
    const float* bk    = (const float*)d_in[6];
    const float* Wv    = (const float*)d_in[7];
    const float* bv    = (const float*)d_in[8];
    const float* Wo    = (const float*)d_in[9];
    const float* bo    = (const float*)d_in[10];
    float* out = (float*)d_out;

    bf16 *qryh, *qryl, *keyh, *keyl, *valh, *vall;
    bf16 *wqTh, *wqTl, *wkTh, *wkTl, *wvTh, *wvTl, *woTh, *woTl;
    bf16 *qh, *ql, *kh, *kl, *vTh, *vTl, *attnh, *attnl, *cch, *ccl;
    float *v, *sc;
    cudaGetSymbolAddress((void**)&qryh, g_qryh); cudaGetSymbolAddress((void**)&qryl, g_qryl);
    cudaGetSymbolAddress((void**)&keyh, g_keyh); cudaGetSymbolAddress((void**)&keyl, g_keyl);
    cudaGetSymbolAddress((void**)&valh, g_valh); cudaGetSymbolAddress((void**)&vall, g_vall);
    cudaGetSymbolAddress((void**)&wqTh, g_wqTh); cudaGetSymbolAddress((void**)&wqTl, g_wqTl);
    cudaGetSymbolAddress((void**)&wkTh, g_wkTh); cudaGetSymbolAddress((void**)&wkTl, g_wkTl);
    cudaGetSymbolAddress((void**)&wvTh, g_wvTh); cudaGetSymbolAddress((void**)&wvTl, g_wvTl);
    cudaGetSymbolAddress((void**)&woTh, g_woTh); cudaGetSymbolAddress((void**)&woTl, g_woTl);
    cudaGetSymbolAddress((void**)&qh,   g_qh);   cudaGetSymbolAddress((void**)&ql,   g_ql);
    cudaGetSymbolAddress((void**)&kh,   g_kh);   cudaGetSymbolAddress((void**)&kl,   g_kl);
    cudaGetSymbolAddress((void**)&vTh,  g_vTh);  cudaGetSymbolAddress((void**)&vTl,  g_vTl);
    cudaGetSymbolAddress((void**)&attnh, g_attnh);
    cudaGetSymbolAddress((void**)&attnl, g_attnl);
    cudaGetSymbolAddress((void**)&cch,  g_cch);  cudaGetSymbolAddress((void**)&ccl,  g_ccl);
    cudaGetSymbolAddress((void**)&v,    g_v);
    cudaGetSymbolAddress((void**)&sc,   g_sc);

    cudaFuncSetAttribute(mma_gemm<3,0>, cudaFuncAttributeMaxDynamicSharedMemorySize, GSMEM);
    cudaFuncSetAttribute(mma_gemm<3,1>, cudaFuncAttributeMaxDynamicSharedMemorySize, GSMEM);

    const float inv_sqrt_dk = 0.088388347648318447f;  // 1/sqrt(128)

    // 0) split inputs into bf16 hi/lo planes
    {
        const int n8 = SEQ * DMODEL / 8;
        cvt_kernel<<<n8 / 256, 256>>>((const float4*)query, (uint4*)qryh, (uint4*)qryl, n8);
        cvt_kernel<<<n8 / 256, 256>>>((const float4*)key_,  (uint4*)keyh, (uint4*)keyl, n8);
        cvt_kernel<<<n8 / 256, 256>>>((const float4*)value, (uint4*)valh, (uint4*)vall, n8);
    }
    // 0b) transpose+split weights
    {
        dim3 g(DKH / 32, DMODEL / 32, NHEADS);
        transpose_cvt_kernel<<<g, 256>>>(Wq, wqTh, wqTl, (long)DMODEL * DKH, DKH, (long)DKH * DMODEL, DMODEL);
        transpose_cvt_kernel<<<g, 256>>>(Wk, wkTh, wkTl, (long)DMODEL * DKH, DKH, (long)DKH * DMODEL, DMODEL);
        transpose_cvt_kernel<<<g, 256>>>(Wv, wvTh, wvTl, (long)DMODEL * DKH, DKH, (long)DKH * DMODEL, DMODEL);
        dim3 go(DMODEL / 32, DMODEL / 32, 1);
        transpose_cvt_kernel<<<go, 256>>>(Wo, woTh, woTl, 0L, DMODEL, 0L, DMODEL);
    }

    // 1) projections
    {
        dim3 g(1, SEQ / 128, NHEADS);
        mma_gemm<3,1><<<g, 256, GSMEM>>>(qryh, qryl, wqTh, wqTl, bq, nullptr, qh, ql,
                                         DMODEL, DMODEL, 0L, DMODEL, (long)DKH * DMODEL,
                                         DMODEL, 128L, 128L, 1.0f, 1);
        mma_gemm<3,1><<<g, 256, GSMEM>>>(keyh, keyl, wkTh, wkTl, bk, nullptr, kh, kl,
                                         DMODEL, DMODEL, 0L, DMODEL, (long)DKH * DMODEL,
                                         DMODEL, 128L, 128L, 1.0f, 1);
        mma_gemm<3,0><<<g, 256, GSMEM>>>(valh, vall, wvTh, wvTl, bv, v, nullptr, nullptr,
                                         DMODEL, DMODEL, 0L, DMODEL, (long)DKH * DMODEL,
                                         DMODEL, 128L, 128L, 1.0f, 1);
    }

    // 2) vT planes: v [t][h*128+n] -> [h][n][t]
    {
        dim3 g(DKH / 32, SEQ / 32, NHEADS);
        transpose_cvt_kernel<<<g, 256>>>(v, vTh, vTl, (long)DKH, DMODEL, (long)DKH * SEQ, SEQ);
    }

    // 3) scores[h][s][t] = q_h[s,:].k_h[t,:] / sqrt(dk)   (fp32)
    {
        dim3 g(SEQ / 128, SEQ / 128, NHEADS);
        mma_gemm<3,0><<<g, 256, GSMEM>>>(qh, ql, kh, kl, bq /*unused*/, sc, nullptr, nullptr,
                                         DKH, DMODEL, 128L, DMODEL, 128L,
                                         SEQ, (long)SEQ * SEQ, 0L, inv_sqrt_dk, 0);
    }

    // 4) softmax over query axis -> bf16 hi/lo attn planes
    {
        dim3 g(SEQ / 128, NHEADS);
        colsoftmax_kernel<<<g, 128>>>(sc, attnh, attnl);
    }

    // 5) concat = attn @ v  (3-pass: attn hi/lo x v hi/lo)
    {
        dim3 g(1, SEQ / 128, NHEADS);
        mma_gemm<3,1><<<g, 256, GSMEM>>>(attnh, attnl, vTh, vTl, bq /*unused*/, nullptr, cch, ccl,
                                         SEQ, SEQ, (long)SEQ * SEQ, SEQ, (long)DKH * SEQ,
                                         DMODEL, 128L, 0L, 1.0f, 0);
    }

    // 6) out = concat @ Wo + bo  (fp32)
    {
        dim3 g(DMODEL / 128, SEQ / 128, 1);
        mma_gemm<3,0><<<g, 256, GSMEM>>>(cch, ccl, woTh, woTl, bo, out, nullptr, nullptr,
                                         DMODEL, DMODEL, 0L, DMODEL, 0L,
                                         DMODEL, 0L, 0L, 1.0f, 1);
    }
}

// round 8
// speedup vs baseline: 1.5582x; 1.5449x over previous
#include <cuda_runtime.h>
#include <cuda_fp16.h>
#include <math.h>

#define SEQ    2048
#define DMODEL 2048
#define NHEADS 16
#define DKH    128
typedef __half fp16;

// ------------------------- scratch (device globals) -------------------------
__device__ fp16 g_qry[SEQ * DMODEL];
__device__ fp16 g_key[SEQ * DMODEL];
__device__ fp16 g_val[SEQ * DMODEL];
__device__ fp16 g_wqT[NHEADS * DKH * DMODEL];           // [h][n][d]
__device__ fp16 g_wkT[NHEADS * DKH * DMODEL];
__device__ fp16 g_wvT[NHEADS * DKH * DMODEL];
__device__ fp16 g_woT[DMODEL * DMODEL];                 // [n][k]
__device__ fp16 g_q[SEQ * DMODEL];                      // [s][h*128+n]
__device__ fp16 g_k[SEQ * DMODEL];
__device__ float g_v[SEQ * DMODEL];
__device__ fp16 g_vT[NHEADS * DKH * SEQ];               // [h][n][t]
__device__ float g_sc[(size_t)NHEADS * SEQ * SEQ];      // fp32 scores [h][s][t]
__device__ fp16 g_attn[(size_t)NHEADS * SEQ * SEQ];     // fp16 attn [h][s][t]
__device__ fp16 g_cc[SEQ * DMODEL];                     // [s][h*128+n]

// ------------------------- helpers -------------------------
__device__ __forceinline__ unsigned smem_u32(const void* p) {
    unsigned a;
    asm("{ .reg .u64 t; cvta.to.shared.u64 t, %1; cvt.u32.u64 %0, t; }" : "=r"(a) : "l"(p));
    return a;
}
// swizzle for 64-byte rows: conflict-free for cp.async granules AND ldmatrix reads
__device__ __forceinline__ unsigned swz(unsigned o) {
    return o ^ ((((o >> 7) & 1u) << 5) | (((o >> 8) & 1u) << 4));
}
__device__ __forceinline__ void ldsm4(unsigned* r, unsigned addr) {
    asm volatile("ldmatrix.sync.aligned.m8n8.x4.shared.b16 {%0,%1,%2,%3}, [%4];"
        : "=r"(r[0]), "=r"(r[1]), "=r"(r[2]), "=r"(r[3]) : "r"(addr));
}
__device__ __forceinline__ void mma16816(float* d, const unsigned* a, unsigned b0, unsigned b1) {
    asm volatile("mma.sync.aligned.m16n8k16.row.col.f32.f16.f16.f32 "
        "{%0,%1,%2,%3}, {%4,%5,%6,%7}, {%8,%9}, {%0,%1,%2,%3};"
        : "+f"(d[0]), "+f"(d[1]), "+f"(d[2]), "+f"(d[3])
        : "r"(a[0]), "r"(a[1]), "r"(a[2]), "r"(a[3]), "r"(b0), "r"(b1));
}
__device__ __forceinline__ void cp16(unsigned dst, const void* src) {
    asm volatile("cp.async.cg.shared.global [%0], [%1], 16;" :: "r"(dst), "l"(src));
}
#define CP_COMMIT() asm volatile("cp.async.commit_group;" ::: "memory")
#define CP_WAIT(n)  asm volatile("cp.async.wait_group %0;" :: "n"(n) : "memory")

__device__ __forceinline__ unsigned pack_h2(float lo, float hi) {
    half2 h = __float22half2_rn(make_float2(lo, hi));
    return *(unsigned*)&h;
}

// ------------------------- fp16 single-pass pipelined warp-MMA GEMM -------------------------
// C[z][m,n] = scale * sum_k A[z][m,k]*B[z][n,k] (+ bias[z][n])
// A/B fp16, k-contiguous. EPI: 0 = fp32 C, 1 = fp16 Ch.
#define ST_A 0
#define ST_B 8192
#define ST_STRIDE 16384
#define GSMEM 32768

template<int EPI>
__global__ void __launch_bounds__(256, 2)
mma_gemm(const fp16* __restrict__ A, const fp16* __restrict__ B,
         const float* __restrict__ bias, float* __restrict__ C, fp16* __restrict__ Ch,
         int K, int lda, long abatch, int ldb, long bbatch,
         int ldc, long cbatch, long biasbatch, float scale, int has_bias)
{
    extern __shared__ __align__(1024) char sm[];
    const unsigned sb = smem_u32(sm);
    const int tid  = threadIdx.x;
    const int lane = tid & 31;
    const int wid  = tid >> 5;
    const int wm   = wid & 3;
    const int wn   = wid >> 2;
    const int z    = blockIdx.z;

    A += (long)z * abatch + (long)blockIdx.y * 128 * lda;
    B += (long)z * bbatch + (long)blockIdx.x * 128 * ldb;

    float acc[2][8][4];
#pragma unroll
    for (int mt = 0; mt < 2; mt++)
#pragma unroll
        for (int nt = 0; nt < 8; nt++)
#pragma unroll
            for (int i = 0; i < 4; i++) acc[mt][nt][i] = 0.0f;

    // cp.async coords: row = tid>>1, this thread covers granules gsel, gsel+1
    const int lrow = tid >> 1;
    const int gsel = (tid & 1) * 2;
    const unsigned d0 = swz((unsigned)(lrow * 64 + gsel * 16));
    const unsigned d1 = swz((unsigned)(lrow * 64 + gsel * 16 + 16));
    const long asrc = (long)lrow * lda + gsel * 8;
    const long bsrc = (long)lrow * ldb + gsel * 8;

    // ldmatrix coords
    const int arow = wm * 32 + (lane & 15);
    const int brow = wn * 64 + (lane & 15);
    const unsigned hi16 = (unsigned)((lane >> 4) * 16);

    const int nch = K >> 5;

#define LOAD_CHUNK(st, k0) do {                                                     \
    const unsigned b_ = sb + (st) * ST_STRIDE;                                      \
    cp16(b_ + ST_A + d0, A + asrc + (k0));                                          \
    cp16(b_ + ST_A + d1, A + asrc + (k0) + 8);                                      \
    cp16(b_ + ST_B + d0, B + bsrc + (k0));                                          \
    cp16(b_ + ST_B + d1, B + bsrc + (k0) + 8);                                      \
} while (0)

    LOAD_CHUNK(0, 0);
    CP_COMMIT();

    for (int ch = 0; ch < nch; ch++) {
        if (ch + 1 < nch) {
            LOAD_CHUNK((ch + 1) & 1, (ch + 1) * 32);
            CP_COMMIT();
            CP_WAIT(1);
        } else {
            CP_WAIT(0);
        }
        __syncthreads();

        const unsigned stb = sb + (ch & 1) * ST_STRIDE;
#pragma unroll
        for (int k16 = 0; k16 < 2; k16++) {
            const unsigned kb = (unsigned)(k16 * 32) + hi16;
            unsigned a[2][4];
#pragma unroll
            for (int mt = 0; mt < 2; mt++)
                ldsm4(a[mt], stb + ST_A + swz((unsigned)((arow + mt * 16) * 64) + kb));
#pragma unroll
            for (int g = 0; g < 4; g++) {
                unsigned bh[4];
                ldsm4(bh, stb + ST_B + swz((unsigned)((brow + g * 16) * 64) + kb));
#pragma unroll
                for (int mt = 0; mt < 2; mt++) {
                    mma16816(acc[mt][2*g],   a[mt], bh[0], bh[2]);
                    mma16816(acc[mt][2*g+1], a[mt], bh[1], bh[3]);
                }
            }
        }
        __syncthreads();
    }
#undef LOAD_CHUNK

    // ---------------- epilogue ----------------
    const float* bz = bias + (long)z * biasbatch + (long)blockIdx.x * 128;
    if (EPI == 0) C += (long)z * cbatch + (long)blockIdx.y * 128 * ldc + (long)blockIdx.x * 128;
    else          Ch += (long)z * cbatch + (long)blockIdx.y * 128 * ldc + (long)blockIdx.x * 128;
#pragma unroll
    for (int mt = 0; mt < 2; mt++) {
        const int row = wm * 32 + mt * 16 + (lane >> 2);
#pragma unroll
        for (int nt = 0; nt < 8; nt++) {
            const int col = wn * 64 + nt * 8 + (lane & 3) * 2;
            float b0 = 0.f, b1 = 0.f;
            if (has_bias) { b0 = bz[col]; b1 = bz[col + 1]; }
            float x0 = fmaf(acc[mt][nt][0], scale, b0);
            float x1 = fmaf(acc[mt][nt][1], scale, b1);
            float x2 = fmaf(acc[mt][nt][2], scale, b0);
            float x3 = fmaf(acc[mt][nt][3], scale, b1);
            if (EPI == 0) {
                float2 v01; v01.x = x0; v01.y = x1;
                float2 v23; v23.x = x2; v23.y = x3;
                *(float2*)(C + (long)row * ldc + col)       = v01;
                *(float2*)(C + (long)(row + 8) * ldc + col) = v23;
            } else {
                *(unsigned*)(Ch + (long)row * ldc + col)       = pack_h2(x0, x1);
                *(unsigned*)(Ch + (long)(row + 8) * ldc + col) = pack_h2(x2, x3);
            }
        }
    }
}

// ------------------------- fp32 -> fp16 (flat) -------------------------
__global__ void __launch_bounds__(256)
cvt_kernel(const float4* __restrict__ in, uint4* __restrict__ o, int n8)
{
    const int i = blockIdx.x * 256 + threadIdx.x;
    if (i >= n8) return;
    float4 x0 = in[2*i], x1 = in[2*i + 1];
    uint4 r;
    r.x = pack_h2(x0.x, x0.y);
    r.y = pack_h2(x0.z, x0.w);
    r.z = pack_h2(x1.x, x1.y);
    r.w = pack_h2(x1.z, x1.w);
    o[i] = r;
}

// ------------------------- transpose + cvt: fp32 [r][c] -> fp16 [c][r] -------------------------
__global__ void __launch_bounds__(256)
transpose_cvt_kernel(const float* __restrict__ in, fp16* __restrict__ o,
                     long ibatch, int istride, long obatch, int ostride)
{
    __shared__ float tile[32][33];
    const int z = blockIdx.z;
    in += (long)z * ibatch;
    o  += (long)z * obatch;
    const int c0 = blockIdx.x * 32;
    const int r0 = blockIdx.y * 32;
    const int tx = threadIdx.x & 31;
    const int ty = threadIdx.x >> 5;
#pragma unroll
    for (int j = 0; j < 4; j++)
        tile[ty + 8 * j][tx] = in[(long)(r0 + ty + 8 * j) * istride + c0 + tx];
    __syncthreads();
#pragma unroll
    for (int j = 0; j < 4; j++)
        o[(long)(c0 + ty + 8 * j) * ostride + r0 + tx] = __float2half(tile[tx][ty + 8 * j]);
}

// ------------------------- FMA-only exp -------------------------
__device__ __forceinline__ float fexp(float x) {
    float t = x * 1.4426950408889634f;
    t = fmaxf(t, -125.0f);
    const float k = rintf(t);
    const float f = t - k;
    float p = 1.3333558146e-3f;
    p = fmaf(p, f, 9.6181291076e-3f);
    p = fmaf(p, f, 5.5504108664e-2f);
    p = fmaf(p, f, 2.4022650696e-1f);
    p = fmaf(p, f, 6.9314718056e-1f);
    p = fmaf(p, f, 1.0f);
    return p * __int_as_float(((int)k + 127) << 23);
}

// ------------------------- softmax over s (query axis), fp32 in -> fp16 out -------------------------
__global__ void __launch_bounds__(128)
colsoftmax_kernel(const float* __restrict__ sc, fp16* __restrict__ attn)
{
    const int h = blockIdx.y;
    const int t = blockIdx.x * 128 + threadIdx.x;
    const float* base = sc + (size_t)h * SEQ * SEQ + t;
    fp16* obase = attn + (size_t)h * SEQ * SEQ + t;

    float m0 = -1e30f, m1 = -1e30f, m2 = -1e30f, m3 = -1e30f;
    float s0 = 0.f, s1 = 0.f, s2 = 0.f, s3 = 0.f;
    for (int s = 0; s < SEQ; s += 4) {
        const float v0 = base[(size_t)(s + 0) * SEQ];
        const float v1 = base[(size_t)(s + 1) * SEQ];
        const float v2 = base[(size_t)(s + 2) * SEQ];
        const float v3 = base[(size_t)(s + 3) * SEQ];
        if (v0 > m0) { s0 = s0 * fexp(m0 - v0) + 1.f; m0 = v0; } else s0 += fexp(v0 - m0);
        if (v1 > m1) { s1 = s1 * fexp(m1 - v1) + 1.f; m1 = v1; } else s1 += fexp(v1 - m1);
        if (v2 > m2) { s2 = s2 * fexp(m2 - v2) + 1.f; m2 = v2; } else s2 += fexp(v2 - m2);
        if (v3 > m3) { s3 = s3 * fexp(m3 - v3) + 1.f; m3 = v3; } else s3 += fexp(v3 - m3);
    }
    const float m = fmaxf(fmaxf(m0, m1), fmaxf(m2, m3));
    const float ssum = s0 * fexp(m0 - m) + s1 * fexp(m1 - m) +
                       s2 * fexp(m2 - m) + s3 * fexp(m3 - m);
    const float inv = 1.0f / ssum;
#pragma unroll 4
    for (int s = 0; s < SEQ; s++) {
        const float v = base[(size_t)s * SEQ];
        obase[(size_t)s * SEQ] = __float2half(fexp(v - m) * inv);
    }
}

// ------------------------- launch -------------------------
extern "C" void kernel_launch(void* const* d_in, const int* in_sizes, int n_in,
                              void* d_out, int out_size)
{
    const float* query = (const float*)d_in[0];
    const float* key_  = (const float*)d_in[1];
    const float* value = (const float*)d_in[2];
    const float* Wq    = (const float*)d_in[3];
    const float* bq    = (const float*)d_in[4];
    const float* Wk    = (const float*)d_in[5];
    const float* bk    = (const float*)d_in[6];
    const float* Wv    = (const float*)d_in[7];
    const float* bv    = (const float*)d_in[8];
    const float* Wo    = (const float*)d_in[9];
    const float* bo    = (const float*)d_in[10];
    float* out = (float*)d_out;

    fp16 *qry, *key16, *val, *wqT, *wkT, *wvT, *woT, *q, *k, *vT, *attn, *cc;
    float *v, *sc;
    cudaGetSymbolAddress((void**)&qry,  g_qry);
    cudaGetSymbolAddress((void**)&key16,g_key);
    cudaGetSymbolAddress((void**)&val,  g_val);
    cudaGetSymbolAddress((void**)&wqT,  g_wqT);
    cudaGetSymbolAddress((void**)&wkT,  g_wkT);
    cudaGetSymbolAddress((void**)&wvT,  g_wvT);
    cudaGetSymbolAddress((void**)&woT,  g_woT);
    cudaGetSymbolAddress((void**)&q,    g_q);
    cudaGetSymbolAddress((void**)&k,    g_k);
    cudaGetSymbolAddress((void**)&vT,   g_vT);
    cudaGetSymbolAddress((void**)&attn, g_attn);
    cudaGetSymbolAddress((void**)&cc,   g_cc);
    cudaGetSymbolAddress((void**)&v,    g_v);
    cudaGetSymbolAddress((void**)&sc,   g_sc);

    const float inv_sqrt_dk = 0.088388347648318447f;  // 1/sqrt(128)

    // 0) inputs -> fp16
    {
        const int n8 = SEQ * DMODEL / 8;
        cvt_kernel<<<n8 / 256, 256>>>((const float4*)query, (uint4*)qry,   n8);
        cvt_kernel<<<n8 / 256, 256>>>((const float4*)key_,  (uint4*)key16, n8);
        cvt_kernel<<<n8 / 256, 256>>>((const float4*)value, (uint4*)val,   n8);
    }
    // 0b) transpose+cvt weights: Wx [h][d][n] -> [h][n][d];  Wo [k][n] -> [n][k]
    {
        dim3 g(DKH / 32, DMODEL / 32, NHEADS);
        transpose_cvt_kernel<<<g, 256>>>(Wq, wqT, (long)DMODEL * DKH, DKH, (long)DKH * DMODEL, DMODEL);
        transpose_cvt_kernel<<<g, 256>>>(Wk, wkT, (long)DMODEL * DKH, DKH, (long)DKH * DMODEL, DMODEL);
        transpose_cvt_kernel<<<g, 256>>>(Wv, wvT, (long)DMODEL * DKH, DKH, (long)DKH * DMODEL, DMODEL);
        dim3 go(DMODEL / 32, DMODEL / 32, 1);
        transpose_cvt_kernel<<<go, 256>>>(Wo, woT, 0L, DMODEL, 0L, DMODEL);
    }

    // 1) projections
    {
        dim3 g(1, SEQ / 128, NHEADS);
        mma_gemm<1><<<g, 256, GSMEM>>>(qry, wqT, bq, nullptr, q,
                                       DMODEL, DMODEL, 0L, DMODEL, (long)DKH * DMODEL,
                                       DMODEL, 128L, 128L, 1.0f, 1);
        mma_gemm<1><<<g, 256, GSMEM>>>(key16, wkT, bk, nullptr, k,
                                       DMODEL, DMODEL, 0L, DMODEL, (long)DKH * DMODEL,
                                       DMODEL, 128L, 128L, 1.0f, 1);
        mma_gemm<0><<<g, 256, GSMEM>>>(val, wvT, bv, v, nullptr,
                                       DMODEL, DMODEL, 0L, DMODEL, (long)DKH * DMODEL,
                                       DMODEL, 128L, 128L, 1.0f, 1);
    }

    // 2) vT: v [t][h*128+n] -> fp16 [h][n][t]
    {
        dim3 g(DKH / 32, SEQ / 32, NHEADS);
        transpose_cvt_kernel<<<g, 256>>>(v, vT, (long)DKH, DMODEL, (long)DKH * SEQ, SEQ);
    }

    // 3) scores[h][s][t] = q_h[s,:].k_h[t,:] / sqrt(dk)   (fp32 out)
    {
        dim3 g(SEQ / 128, SEQ / 128, NHEADS);
        mma_gemm<0><<<g, 256, GSMEM>>>(q, k, bq /*unused*/, sc, nullptr,
                                       DKH, DMODEL, 128L, DMODEL, 128L,
                                       SEQ, (long)SEQ * SEQ, 0L, inv_sqrt_dk, 0);
    }

    // 4) softmax over query axis -> fp16 attn
    {
        dim3 g(SEQ / 128, NHEADS);
        colsoftmax_kernel<<<g, 128>>>(sc, attn);
    }

    // 5) concat = attn @ v  -> fp16
    {
        dim3 g(1, SEQ / 128, NHEADS);
        mma_gemm<1><<<g, 256, GSMEM>>>(attn, vT, bq /*unused*/, nullptr, cc,
                                       SEQ, SEQ, (long)SEQ * SEQ, SEQ, (long)DKH * SEQ,
                                       DMODEL, 128L, 0L, 1.0f, 0);
    }

    // 6) out = concat @ Wo + bo  (fp32)
    {
        dim3 g(DMODEL / 128, SEQ / 128, 1);
        mma_gemm<0><<<g, 256, GSMEM>>>(cc, woT, bo, out, nullptr,
                                       DMODEL, DMODEL, 0L, DMODEL, 0L,
                                       DMODEL, 0L, 0L, 1.0f, 1);
    }
}

// round 9
// speedup vs baseline: 1.7491x; 1.1225x over previous
#include <cuda_runtime.h>
#include <cuda_fp16.h>
#include <math.h>

#define SEQ    2048
#define DMODEL 2048
#define NHEADS 16
#define DKH    128
typedef __half fp16;

// ------------------------- scratch (device globals) -------------------------
__device__ fp16 g_in16[3 * SEQ * DMODEL];                 // [i][s][d]  (qry, key, val fp16)
__device__ fp16 g_wT[3 * NHEADS * DKH * DMODEL];          // [i][h][n][d]
__device__ fp16 g_woT[DMODEL * DMODEL];                   // [n][k]
__device__ float g_bias[3 * DMODEL];                      // [i][h*128+n]
__device__ fp16 g_qkv[3 * SEQ * DMODEL];                  // [i][s][h*128+n]
__device__ fp16 g_vT[NHEADS * DKH * SEQ];                 // [h][n][t]
__device__ float g_sc[(size_t)NHEADS * SEQ * SEQ];        // fp32 scores [h][s][t]
__device__ fp16 g_attn[(size_t)NHEADS * SEQ * SEQ];       // fp16 attn [h][s][t]
__device__ fp16 g_cc[SEQ * DMODEL];                       // [s][h*128+n]

// ------------------------- helpers -------------------------
__device__ __forceinline__ unsigned smem_u32(const void* p) {
    unsigned a;
    asm("{ .reg .u64 t; cvta.to.shared.u64 t, %1; cvt.u32.u64 %0, t; }" : "=r"(a) : "l"(p));
    return a;
}
// SW128 for 128-byte rows (8 x 16B granules): granule idx ^= row & 7
__device__ __forceinline__ unsigned swz(unsigned o) {
    return o ^ (((o >> 7) & 7u) << 4);
}
__device__ __forceinline__ void ldsm4(unsigned* r, unsigned addr) {
    asm volatile("ldmatrix.sync.aligned.m8n8.x4.shared.b16 {%0,%1,%2,%3}, [%4];"
        : "=r"(r[0]), "=r"(r[1]), "=r"(r[2]), "=r"(r[3]) : "r"(addr));
}
__device__ __forceinline__ void mma16816(float* d, const unsigned* a, unsigned b0, unsigned b1) {
    asm volatile("mma.sync.aligned.m16n8k16.row.col.f32.f16.f16.f32 "
        "{%0,%1,%2,%3}, {%4,%5,%6,%7}, {%8,%9}, {%0,%1,%2,%3};"
        : "+f"(d[0]), "+f"(d[1]), "+f"(d[2]), "+f"(d[3])
        : "r"(a[0]), "r"(a[1]), "r"(a[2]), "r"(a[3]), "r"(b0), "r"(b1));
}
__device__ __forceinline__ void cp16(unsigned dst, const void* src) {
    asm volatile("cp.async.cg.shared.global [%0], [%1], 16;" :: "r"(dst), "l"(src));
}
#define CP_COMMIT() asm volatile("cp.async.commit_group;" ::: "memory")
#define CP_WAIT(n)  asm volatile("cp.async.wait_group %0;" :: "n"(n) : "memory")

__device__ __forceinline__ unsigned pack_h2(float lo, float hi) {
    half2 h = __float22half2_rn(make_float2(lo, hi));
    return *(unsigned*)&h;
}

// ------------------------- fp16 warp-MMA GEMM -------------------------
// C[z][m,n] = scale * sum_k A[z][m,k]*B[z][n,k] (+ bias[z][n])
// Block tile 64(M) x 128(N), K-chunk 64, 128 threads (4 warps, 2x2 of 32x64), occ 4.
// MODE 0: fp32 C.  MODE 1: fp16 Ch.  MODE 2: merged projections (z = i*16+h), fp16 Ch.
#define BM 64
#define BN 128
#define BKC 64
#define ST_A 0
#define ST_B 8192
#define ST_STRIDE 24576
#define GSMEM 49152

template<int MODE>
__global__ void __launch_bounds__(128, 4)
mma_gemm(const fp16* __restrict__ A, const fp16* __restrict__ B,
         const float* __restrict__ bias, float* __restrict__ C, fp16* __restrict__ Ch,
         int K, int lda, long abatch, int ldb, long bbatch,
         int ldc, long cbatch, long biasbatch, float scale, int has_bias)
{
    extern __shared__ __align__(1024) char sm[];
    const unsigned sb = smem_u32(sm);
    const int tid  = threadIdx.x;
    const int lane = tid & 31;
    const int wid  = tid >> 5;
    const int wm   = wid & 1;         // 2 x 32 rows
    const int wn   = wid >> 1;        // 2 x 64 cols
    const int z    = blockIdx.z;

    long coff;
    long boff_bias;
    if (MODE == 2) {
        const int ip = z >> 4;        // input selector (q/k/v)
        const int h  = z & 15;        // head
        A += (long)ip * abatch + (long)blockIdx.y * BM * lda;
        B += (long)z * bbatch;
        coff = (long)ip * cbatch + (long)h * 128 + (long)blockIdx.y * BM * ldc;
        boff_bias = (long)z * 128;
    } else {
        A += (long)z * abatch + (long)blockIdx.y * BM * lda;
        B += (long)z * bbatch + (long)blockIdx.x * BN * ldb;
        coff = (long)z * cbatch + (long)blockIdx.y * BM * ldc + (long)blockIdx.x * BN;
        boff_bias = (long)z * biasbatch + (long)blockIdx.x * BN;
    }

    float acc[2][8][4];
#pragma unroll
    for (int mt = 0; mt < 2; mt++)
#pragma unroll
        for (int nt = 0; nt < 8; nt++)
#pragma unroll
            for (int i = 0; i < 4; i++) acc[mt][nt][i] = 0.0f;

    // cp.async coords: granule = 16B = 8 fp16. rows r0 + 16i, granule g.
    const int r0 = tid >> 3;          // 0..15
    const int g  = tid & 7;           // 0..7
    const unsigned dbase = swz((unsigned)(r0 * 128 + g * 16));
    const long sa = (long)r0 * lda + g * 8;
    const long sbk = (long)r0 * ldb + g * 8;

    // ldmatrix coords (row-constant swizzle folded in)
    const int hi = lane >> 4;         // 0/1 -> +8 cols
    const int arow[2] = { wm * 32 + (lane & 15), wm * 32 + 16 + (lane & 15) };
    const int brow[4] = { wn * 64 + (lane & 15),      wn * 64 + 16 + (lane & 15),
                          wn * 64 + 32 + (lane & 15), wn * 64 + 48 + (lane & 15) };

    const int nch = K >> 6;

#define LOAD_CHUNK(st, k0) do {                                                     \
    const unsigned b_ = sb + (st) * ST_STRIDE;                                      \
    _Pragma("unroll")                                                               \
    for (int i = 0; i < 4; i++)                                                     \
        cp16(b_ + ST_A + dbase + i * 2048, A + sa + (long)i * 16 * lda + (k0));     \
    _Pragma("unroll")                                                               \
    for (int i = 0; i < 8; i++)                                                     \
        cp16(b_ + ST_B + dbase + i * 2048, B + sbk + (long)i * 16 * ldb + (k0));    \
} while (0)

    LOAD_CHUNK(0, 0);
    CP_COMMIT();

    for (int ch = 0; ch < nch; ch++) {
        if (ch + 1 < nch) {
            LOAD_CHUNK((ch + 1) & 1, (ch + 1) * BKC);
            CP_COMMIT();
            CP_WAIT(1);
        } else {
            CP_WAIT(0);
        }
        __syncthreads();

        const unsigned stb = sb + (ch & 1) * ST_STRIDE;
#pragma unroll
        for (int kk = 0; kk < 4; kk++) {
            const int cg = kk * 2 + hi;   // granule column 0..7
            unsigned a[2][4];
#pragma unroll
            for (int mt = 0; mt < 2; mt++) {
                const unsigned off = (unsigned)(arow[mt] * 128 + ((cg ^ (arow[mt] & 7)) * 16));
                ldsm4(a[mt], stb + ST_A + off);
            }
#pragma unroll
            for (int g4 = 0; g4 < 4; g4++) {
                const unsigned off = (unsigned)(brow[g4] * 128 + ((cg ^ (brow[g4] & 7)) * 16));
                unsigned bh[4];
                ldsm4(bh, stb + ST_B + off);
#pragma unroll
                for (int mt = 0; mt < 2; mt++) {
                    mma16816(acc[mt][2*g4],   a[mt], bh[0], bh[2]);
                    mma16816(acc[mt][2*g4+1], a[mt], bh[1], bh[3]);
                }
            }
        }
        __syncthreads();
    }
#undef LOAD_CHUNK

    // ---------------- epilogue ----------------
    const float* bz = bias + boff_bias;
#pragma unroll
    for (int mt = 0; mt < 2; mt++) {
        const int row = wm * 32 + mt * 16 + (lane >> 2);
#pragma unroll
        for (int nt = 0; nt < 8; nt++) {
            const int col = wn * 64 + nt * 8 + (lane & 3) * 2;
            float b0 = 0.f, b1 = 0.f;
            if (has_bias) { b0 = bz[col]; b1 = bz[col + 1]; }
            float x0 = fmaf(acc[mt][nt][0], scale, b0);
            float x1 = fmaf(acc[mt][nt][1], scale, b1);
            float x2 = fmaf(acc[mt][nt][2], scale, b0);
            float x3 = fmaf(acc[mt][nt][3], scale, b1);
            if (MODE == 0) {
                float2 v01; v01.x = x0; v01.y = x1;
                float2 v23; v23.x = x2; v23.y = x3;
                *(float2*)(C + coff + (long)row * ldc + col)       = v01;
                *(float2*)(C + coff + (long)(row + 8) * ldc + col) = v23;
            } else {
                *(unsigned*)(Ch + coff + (long)row * ldc + col)       = pack_h2(x0, x1);
                *(unsigned*)(Ch + coff + (long)(row + 8) * ldc + col) = pack_h2(x2, x3);
            }
        }
    }
}

// ------------------------- fp32 -> fp16 (flat) -------------------------
__global__ void __launch_bounds__(256)
cvt_kernel(const float4* __restrict__ in, uint4* __restrict__ o, int n8)
{
    const int i = blockIdx.x * 256 + threadIdx.x;
    if (i >= n8) return;
    float4 x0 = in[2*i], x1 = in[2*i + 1];
    uint4 r;
    r.x = pack_h2(x0.x, x0.y);
    r.y = pack_h2(x0.z, x0.w);
    r.z = pack_h2(x1.x, x1.y);
    r.w = pack_h2(x1.z, x1.w);
    o[i] = r;
}

// ------------------------- transpose + cvt: fp32 [r][c] -> fp16 [c][r] -------------------------
__global__ void __launch_bounds__(256)
transpose_cvt_kernel(const float* __restrict__ in, fp16* __restrict__ o,
                     long ibatch, int istride, long obatch, int ostride)
{
    __shared__ float tile[32][33];
    const int z = blockIdx.z;
    in += (long)z * ibatch;
    o  += (long)z * obatch;
    const int c0 = blockIdx.x * 32;
    const int r0 = blockIdx.y * 32;
    const int tx = threadIdx.x & 31;
    const int ty = threadIdx.x >> 5;
#pragma unroll
    for (int j = 0; j < 4; j++)
        tile[ty + 8 * j][tx] = in[(long)(r0 + ty + 8 * j) * istride + c0 + tx];
    __syncthreads();
#pragma unroll
    for (int j = 0; j < 4; j++)
        o[(long)(c0 + ty + 8 * j) * ostride + r0 + tx] = __float2half(tile[tx][ty + 8 * j]);
}

// ------------------------- transpose fp16 -> fp16 -------------------------
__global__ void __launch_bounds__(256)
transpose_h_kernel(const fp16* __restrict__ in, fp16* __restrict__ o,
                   long ibatch, int istride, long obatch, int ostride)
{
    __shared__ fp16 tile[32][34];
    const int z = blockIdx.z;
    in += (long)z * ibatch;
    o  += (long)z * obatch;
    const int c0 = blockIdx.x * 32;
    const int r0 = blockIdx.y * 32;
    const int tx = threadIdx.x & 31;
    const int ty = threadIdx.x >> 5;
#pragma unroll
    for (int j = 0; j < 4; j++)
        tile[ty + 8 * j][tx] = in[(long)(r0 + ty + 8 * j) * istride + c0 + tx];
    __syncthreads();
#pragma unroll
    for (int j = 0; j < 4; j++)
        o[(long)(c0 + ty + 8 * j) * ostride + r0 + tx] = tile[tx][ty + 8 * j];
}

// ------------------------- FMA-only exp -------------------------
__device__ __forceinline__ float fexp(float x) {
    float t = x * 1.4426950408889634f;
    t = fmaxf(t, -125.0f);
    const float k = rintf(t);
    const float f = t - k;
    float p = 1.3333558146e-3f;
    p = fmaf(p, f, 9.6181291076e-3f);
    p = fmaf(p, f, 5.5504108664e-2f);
    p = fmaf(p, f, 2.4022650696e-1f);
    p = fmaf(p, f, 6.9314718056e-1f);
    p = fmaf(p, f, 1.0f);
    return p * __int_as_float(((int)k + 127) << 23);
}

// ------------------------- softmax over s (query axis), fp32 in -> fp16 out -------------------------
__global__ void __launch_bounds__(128)
colsoftmax_kernel(const float* __restrict__ sc, fp16* __restrict__ attn)
{
    const int h = blockIdx.y;
    const int t = blockIdx.x * 128 + threadIdx.x;
    const float* base = sc + (size_t)h * SEQ * SEQ + t;
    fp16* obase = attn + (size_t)h * SEQ * SEQ + t;

    float m0 = -1e30f, m1 = -1e30f, m2 = -1e30f, m3 = -1e30f;
    float s0 = 0.f, s1 = 0.f, s2 = 0.f, s3 = 0.f;
    for (int s = 0; s < SEQ; s += 4) {
        const float v0 = base[(size_t)(s + 0) * SEQ];
        const float v1 = base[(size_t)(s + 1) * SEQ];
        const float v2 = base[(size_t)(s + 2) * SEQ];
        const float v3 = base[(size_t)(s + 3) * SEQ];
        if (v0 > m0) { s0 = s0 * fexp(m0 - v0) + 1.f; m0 = v0; } else s0 += fexp(v0 - m0);
        if (v1 > m1) { s1 = s1 * fexp(m1 - v1) + 1.f; m1 = v1; } else s1 += fexp(v1 - m1);
        if (v2 > m2) { s2 = s2 * fexp(m2 - v2) + 1.f; m2 = v2; } else s2 += fexp(v2 - m2);
        if (v3 > m3) { s3 = s3 * fexp(m3 - v3) + 1.f; m3 = v3; } else s3 += fexp(v3 - m3);
    }
    const float m = fmaxf(fmaxf(m0, m1), fmaxf(m2, m3));
    const float ssum = s0 * fexp(m0 - m) + s1 * fexp(m1 - m) +
                       s2 * fexp(m2 - m) + s3 * fexp(m3 - m);
    const float inv = 1.0f / ssum;
#pragma unroll 4
    for (int s = 0; s < SEQ; s++) {
        const float v = base[(size_t)s * SEQ];
        obase[(size_t)s * SEQ] = __float2half(fexp(v - m) * inv);
    }
}

// ------------------------- launch -------------------------
extern "C" void kernel_launch(void* const* d_in, const int* in_sizes, int n_in,
                              void* d_out, int out_size)
{
    const float* query = (const float*)d_in[0];
    const float* key_  = (const float*)d_in[1];
    const float* value = (const float*)d_in[2];
    const float* Wq    = (const float*)d_in[3];
    const float* bq    = (const float*)d_in[4];
    const float* Wk    = (const float*)d_in[5];
    const float* bk    = (const float*)d_in[6];
    const float* Wv    = (const float*)d_in[7];
    const float* bv    = (const float*)d_in[8];
    const float* Wo    = (const float*)d_in[9];
    const float* bo    = (const float*)d_in[10];
    float* out = (float*)d_out;

    fp16 *in16, *wT, *woT, *qkv, *vT, *attn, *cc;
    float *bias, *sc;
    cudaGetSymbolAddress((void**)&in16, g_in16);
    cudaGetSymbolAddress((void**)&wT,   g_wT);
    cudaGetSymbolAddress((void**)&woT,  g_woT);
    cudaGetSymbolAddress((void**)&bias, g_bias);
    cudaGetSymbolAddress((void**)&qkv,  g_qkv);
    cudaGetSymbolAddress((void**)&vT,   g_vT);
    cudaGetSymbolAddress((void**)&attn, g_attn);
    cudaGetSymbolAddress((void**)&cc,   g_cc);
    cudaGetSymbolAddress((void**)&sc,   g_sc);

    cudaFuncSetAttribute(mma_gemm<0>, cudaFuncAttributeMaxDynamicSharedMemorySize, GSMEM);
    cudaFuncSetAttribute(mma_gemm<1>, cudaFuncAttributeMaxDynamicSharedMemorySize, GSMEM);
    cudaFuncSetAttribute(mma_gemm<2>, cudaFuncAttributeMaxDynamicSharedMemorySize, GSMEM);

    const float inv_sqrt_dk = 0.088388347648318447f;  // 1/sqrt(128)
    const long PLANE = (long)SEQ * DMODEL;
    const long WPLANE = (long)NHEADS * DKH * DMODEL;

    // 0) inputs -> fp16 planes
    {
        const int n8 = SEQ * DMODEL / 8;
        cvt_kernel<<<n8 / 256, 256>>>((const float4*)query, (uint4*)(in16 + 0 * PLANE), n8);
        cvt_kernel<<<n8 / 256, 256>>>((const float4*)key_,  (uint4*)(in16 + 1 * PLANE), n8);
        cvt_kernel<<<n8 / 256, 256>>>((const float4*)value, (uint4*)(in16 + 2 * PLANE), n8);
    }
    // 0b) transpose+cvt weights: Wx [h][d][n] -> [i][h][n][d];  Wo [k][n] -> [n][k]
    {
        dim3 g(DKH / 32, DMODEL / 32, NHEADS);
        transpose_cvt_kernel<<<g, 256>>>(Wq, wT + 0 * WPLANE, (long)DMODEL * DKH, DKH, (long)DKH * DMODEL, DMODEL);
        transpose_cvt_kernel<<<g, 256>>>(Wk, wT + 1 * WPLANE, (long)DMODEL * DKH, DKH, (long)DKH * DMODEL, DMODEL);
        transpose_cvt_kernel<<<g, 256>>>(Wv, wT + 2 * WPLANE, (long)DMODEL * DKH, DKH, (long)DKH * DMODEL, DMODEL);
        dim3 go(DMODEL / 32, DMODEL / 32, 1);
        transpose_cvt_kernel<<<go, 256>>>(Wo, woT, 0L, DMODEL, 0L, DMODEL);
    }
    // 0c) pack biases into one buffer
    cudaMemcpyAsync(bias + 0 * DMODEL, bq, DMODEL * sizeof(float), cudaMemcpyDeviceToDevice);
    cudaMemcpyAsync(bias + 1 * DMODEL, bk, DMODEL * sizeof(float), cudaMemcpyDeviceToDevice);
    cudaMemcpyAsync(bias + 2 * DMODEL, bv, DMODEL * sizeof(float), cudaMemcpyDeviceToDevice);

    // 1) merged projections: z = i*16 + h, grid (1, 32, 48)
    {
        dim3 g(1, SEQ / BM, 48);
        mma_gemm<2><<<g, 128, GSMEM>>>(in16, wT, bias, nullptr, qkv,
                                       DMODEL, DMODEL, PLANE, DMODEL, (long)DKH * DMODEL,
                                       DMODEL, PLANE, 0L, 1.0f, 1);
    }

    // 2) vT: qkv plane 2 [t][h*128+n] -> [h][n][t]
    {
        dim3 g(DKH / 32, SEQ / 32, NHEADS);
        transpose_h_kernel<<<g, 256>>>(qkv + 2 * PLANE, vT, (long)DKH, DMODEL, (long)DKH * SEQ, SEQ);
    }

    // 3) scores[h][s][t] = q_h[s,:].k_h[t,:] / sqrt(dk)  (fp32 out)
    {
        dim3 g(SEQ / BN, SEQ / BM, NHEADS);
        mma_gemm<0><<<g, 128, GSMEM>>>(qkv + 0 * PLANE, qkv + 1 * PLANE, bias /*unused*/, sc, nullptr,
                                       DKH, DMODEL, 128L, DMODEL, 128L,
                                       SEQ, (long)SEQ * SEQ, 0L, inv_sqrt_dk, 0);
    }

    // 4) softmax over query axis -> fp16 attn
    {
        dim3 g(SEQ / 128, NHEADS);
        colsoftmax_kernel<<<g, 128>>>(sc, attn);
    }

    // 5) concat = attn @ v -> fp16
    {
        dim3 g(1, SEQ / BM, NHEADS);
        mma_gemm<1><<<g, 128, GSMEM>>>(attn, vT, bias /*unused*/, nullptr, cc,
                                       SEQ, SEQ, (long)SEQ * SEQ, SEQ, (long)DKH * SEQ,
                                       DMODEL, 128L, 0L, 1.0f, 0);
    }

    // 6) out = concat @ Wo + bo  (fp32)
    {
        dim3 g(DMODEL / BN, SEQ / BM, 1);
        mma_gemm<0><<<g, 128, GSMEM>>>(cc, woT, bo, out, nullptr,
                                       DMODEL, DMODEL, 0L, DMODEL, 0L,
                                       DMODEL, 0L, 0L, 1.0f, 1);
    }
}

// round 10
// speedup vs baseline: 4.0086x; 2.2918x over previous
#include <cuda_runtime.h>
#include <cuda_fp16.h>
#include <math.h>

#define SEQ    2048
#define DMODEL 2048
#define NHEADS 16
#define DKH    128
typedef __half fp16;

// ------------------------- scratch (device globals) -------------------------
__device__ fp16 g_in16[3 * SEQ * DMODEL];                 // [i][s][d]  (qry, key, val fp16)
__device__ fp16 g_wT[3 * NHEADS * DKH * DMODEL];          // [i][h][n][d]
__device__ fp16 g_woT[DMODEL * DMODEL];                   // [n][k]
__device__ float g_bias[3 * DMODEL];                      // [i][h*128+n]
__device__ fp16 g_qkv[3 * SEQ * DMODEL];                  // [i][s][h*128+n]
__device__ fp16 g_vT[NHEADS * DKH * SEQ];                 // [h][n][t]  (pre-scaled by 1/Z)
__device__ fp16 g_E[(size_t)NHEADS * SEQ * SEQ];          // fp16 E=exp(scores) [h][s][t]
__device__ float g_Z[NHEADS * SEQ];                       // column sums [h][t]
__device__ fp16 g_cc[SEQ * DMODEL];                       // [s][h*128+n]

// ------------------------- helpers -------------------------
__device__ __forceinline__ unsigned smem_u32(const void* p) {
    unsigned a;
    asm("{ .reg .u64 t; cvta.to.shared.u64 t, %1; cvt.u32.u64 %0, t; }" : "=r"(a) : "l"(p));
    return a;
}
// SW128 for 128-byte rows (8 x 16B granules): granule idx ^= row & 7
__device__ __forceinline__ unsigned swz(unsigned o) {
    return o ^ (((o >> 7) & 7u) << 4);
}
__device__ __forceinline__ void ldsm4(unsigned* r, unsigned addr) {
    asm volatile("ldmatrix.sync.aligned.m8n8.x4.shared.b16 {%0,%1,%2,%3}, [%4];"
        : "=r"(r[0]), "=r"(r[1]), "=r"(r[2]), "=r"(r[3]) : "r"(addr));
}
__device__ __forceinline__ void mma16816(float* d, const unsigned* a, unsigned b0, unsigned b1) {
    asm volatile("mma.sync.aligned.m16n8k16.row.col.f32.f16.f16.f32 "
        "{%0,%1,%2,%3}, {%4,%5,%6,%7}, {%8,%9}, {%0,%1,%2,%3};"
        : "+f"(d[0]), "+f"(d[1]), "+f"(d[2]), "+f"(d[3])
        : "r"(a[0]), "r"(a[1]), "r"(a[2]), "r"(a[3]), "r"(b0), "r"(b1));
}
__device__ __forceinline__ void cp16(unsigned dst, const void* src) {
    asm volatile("cp.async.cg.shared.global [%0], [%1], 16;" :: "r"(dst), "l"(src));
}
#define CP_COMMIT() asm volatile("cp.async.commit_group;" ::: "memory")
#define CP_WAIT(n)  asm volatile("cp.async.wait_group %0;" :: "n"(n) : "memory")

__device__ __forceinline__ unsigned pack_h2(float lo, float hi) {
    half2 h = __float22half2_rn(make_float2(lo, hi));
    return *(unsigned*)&h;
}

// FMA-only exp (no MUFU pressure)
__device__ __forceinline__ float fexp(float x) {
    float t = x * 1.4426950408889634f;
    t = fmaxf(t, -125.0f);
    const float k = rintf(t);
    const float f = t - k;
    float p = 1.3333558146e-3f;
    p = fmaf(p, f, 9.6181291076e-3f);
    p = fmaf(p, f, 5.5504108664e-2f);
    p = fmaf(p, f, 2.4022650696e-1f);
    p = fmaf(p, f, 6.9314718056e-1f);
    p = fmaf(p, f, 1.0f);
    return p * __int_as_float(((int)k + 127) << 23);
}

// ------------------------- fp16 warp-MMA GEMM -------------------------
// C[z][m,n] = scale * sum_k A[z][m,k]*B[z][n,k] (+ bias[z][n])
// Block tile 64(M) x 128(N), K-chunk 64, 128 threads (4 warps, 2x2 of 32x64), occ 4.
// MODE 0: fp32 C.  MODE 1: fp16 Ch.  MODE 2: merged projections (z = i*16+h), fp16 Ch.
// MODE 3: fp16 Ch = exp(scale * acc)   (scores -> E, softmax numerator)
#define BM 64
#define BN 128
#define BKC 64
#define ST_A 0
#define ST_B 8192
#define ST_STRIDE 24576
#define GSMEM 49152

template<int MODE>
__global__ void __launch_bounds__(128, 4)
mma_gemm(const fp16* __restrict__ A, const fp16* __restrict__ B,
         const float* __restrict__ bias, float* __restrict__ C, fp16* __restrict__ Ch,
         int K, int lda, long abatch, int ldb, long bbatch,
         int ldc, long cbatch, long biasbatch, float scale, int has_bias)
{
    extern __shared__ __align__(1024) char sm[];
    const unsigned sb = smem_u32(sm);
    const int tid  = threadIdx.x;
    const int lane = tid & 31;
    const int wid  = tid >> 5;
    const int wm   = wid & 1;         // 2 x 32 rows
    const int wn   = wid >> 1;        // 2 x 64 cols
    const int z    = blockIdx.z;

    long coff;
    long boff_bias;
    if (MODE == 2) {
        const int ip = z >> 4;        // input selector (q/k/v)
        const int h  = z & 15;        // head
        A += (long)ip * abatch + (long)blockIdx.y * BM * lda;
        B += (long)z * bbatch;
        coff = (long)ip * cbatch + (long)h * 128 + (long)blockIdx.y * BM * ldc;
        boff_bias = (long)z * 128;
    } else {
        A += (long)z * abatch + (long)blockIdx.y * BM * lda;
        B += (long)z * bbatch + (long)blockIdx.x * BN * ldb;
        coff = (long)z * cbatch + (long)blockIdx.y * BM * ldc + (long)blockIdx.x * BN;
        boff_bias = (long)z * biasbatch + (long)blockIdx.x * BN;
    }

    float acc[2][8][4];
#pragma unroll
    for (int mt = 0; mt < 2; mt++)
#pragma unroll
        for (int nt = 0; nt < 8; nt++)
#pragma unroll
            for (int i = 0; i < 4; i++) acc[mt][nt][i] = 0.0f;

    // cp.async coords: granule = 16B = 8 fp16. rows r0 + 16i, granule g.
    const int r0 = tid >> 3;          // 0..15
    const int g  = tid & 7;           // 0..7
    const unsigned dbase = swz((unsigned)(r0 * 128 + g * 16));
    const long sa = (long)r0 * lda + g * 8;
    const long sbk = (long)r0 * ldb + g * 8;

    // ldmatrix coords (row-constant swizzle folded in)
    const int hi = lane >> 4;         // 0/1 -> +8 cols
    const int arow[2] = { wm * 32 + (lane & 15), wm * 32 + 16 + (lane & 15) };
    const int brow[4] = { wn * 64 + (lane & 15),      wn * 64 + 16 + (lane & 15),
                          wn * 64 + 32 + (lane & 15), wn * 64 + 48 + (lane & 15) };

    const int nch = K >> 6;

#define LOAD_CHUNK(st, k0) do {                                                     \
    const unsigned b_ = sb + (st) * ST_STRIDE;                                      \
    _Pragma("unroll")                                                               \
    for (int i = 0; i < 4; i++)                                                     \
        cp16(b_ + ST_A + dbase + i * 2048, A + sa + (long)i * 16 * lda + (k0));     \
    _Pragma("unroll")                                                               \
    for (int i = 0; i < 8; i++)                                                     \
        cp16(b_ + ST_B + dbase + i * 2048, B + sbk + (long)i * 16 * ldb + (k0));    \
} while (0)

    LOAD_CHUNK(0, 0);
    CP_COMMIT();

    for (int ch = 0; ch < nch; ch++) {
        if (ch + 1 < nch) {
            LOAD_CHUNK((ch + 1) & 1, (ch + 1) * BKC);
            CP_COMMIT();
            CP_WAIT(1);
        } else {
            CP_WAIT(0);
        }
        __syncthreads();

        const unsigned stb = sb + (ch & 1) * ST_STRIDE;
#pragma unroll
        for (int kk = 0; kk < 4; kk++) {
            const int cg = kk * 2 + hi;   // granule column 0..7
            unsigned a[2][4];
#pragma unroll
            for (int mt = 0; mt < 2; mt++) {
                const unsigned off = (unsigned)(arow[mt] * 128 + ((cg ^ (arow[mt] & 7)) * 16));
                ldsm4(a[mt], stb + ST_A + off);
            }
#pragma unroll
            for (int g4 = 0; g4 < 4; g4++) {
                const unsigned off = (unsigned)(brow[g4] * 128 + ((cg ^ (brow[g4] & 7)) * 16));
                unsigned bh[4];
                ldsm4(bh, stb + ST_B + off);
#pragma unroll
                for (int mt = 0; mt < 2; mt++) {
                    mma16816(acc[mt][2*g4],   a[mt], bh[0], bh[2]);
                    mma16816(acc[mt][2*g4+1], a[mt], bh[1], bh[3]);
                }
            }
        }
        __syncthreads();
    }
#undef LOAD_CHUNK

    // ---------------- epilogue ----------------
    const float* bz = bias + boff_bias;
#pragma unroll
    for (int mt = 0; mt < 2; mt++) {
        const int row = wm * 32 + mt * 16 + (lane >> 2);
#pragma unroll
        for (int nt = 0; nt < 8; nt++) {
            const int col = wn * 64 + nt * 8 + (lane & 3) * 2;
            float b0 = 0.f, b1 = 0.f;
            if (has_bias) { b0 = bz[col]; b1 = bz[col + 1]; }
            float x0 = fmaf(acc[mt][nt][0], scale, b0);
            float x1 = fmaf(acc[mt][nt][1], scale, b1);
            float x2 = fmaf(acc[mt][nt][2], scale, b0);
            float x3 = fmaf(acc[mt][nt][3], scale, b1);
            if (MODE == 3) {
                x0 = fexp(x0); x1 = fexp(x1); x2 = fexp(x2); x3 = fexp(x3);
            }
            if (MODE == 0) {
                float2 v01; v01.x = x0; v01.y = x1;
                float2 v23; v23.x = x2; v23.y = x3;
                *(float2*)(C + coff + (long)row * ldc + col)       = v01;
                *(float2*)(C + coff + (long)(row + 8) * ldc + col) = v23;
            } else {
                *(unsigned*)(Ch + coff + (long)row * ldc + col)       = pack_h2(x0, x1);
                *(unsigned*)(Ch + coff + (long)(row + 8) * ldc + col) = pack_h2(x2, x3);
            }
        }
    }
}

// ------------------------- fp32 -> fp16 (flat) -------------------------
__global__ void __launch_bounds__(256)
cvt_kernel(const float4* __restrict__ in, uint4* __restrict__ o, int n8)
{
    const int i = blockIdx.x * 256 + threadIdx.x;
    if (i >= n8) return;
    float4 x0 = in[2*i], x1 = in[2*i + 1];
    uint4 r;
    r.x = pack_h2(x0.x, x0.y);
    r.y = pack_h2(x0.z, x0.w);
    r.z = pack_h2(x1.x, x1.y);
    r.w = pack_h2(x1.z, x1.w);
    o[i] = r;
}

// ------------------------- transpose + cvt: fp32 [r][c] -> fp16 [c][r] -------------------------
__global__ void __launch_bounds__(256)
transpose_cvt_kernel(const float* __restrict__ in, fp16* __restrict__ o,
                     long ibatch, int istride, long obatch, int ostride)
{
    __shared__ float tile[32][33];
    const int z = blockIdx.z;
    in += (long)z * ibatch;
    o  += (long)z * obatch;
    const int c0 = blockIdx.x * 32;
    const int r0 = blockIdx.y * 32;
    const int tx = threadIdx.x & 31;
    const int ty = threadIdx.x >> 5;
#pragma unroll
    for (int j = 0; j < 4; j++)
        tile[ty + 8 * j][tx] = in[(long)(r0 + ty + 8 * j) * istride + c0 + tx];
    __syncthreads();
#pragma unroll
    for (int j = 0; j < 4; j++)
        o[(long)(c0 + ty + 8 * j) * ostride + r0 + tx] = __float2half(tile[tx][ty + 8 * j]);
}

// ------------------------- column sums of E: Z[h][t] = sum_s E[h][s][t] -------------------------
__global__ void __launch_bounds__(256)
colsum_kernel(const fp16* __restrict__ E, float* __restrict__ Z)
{
    const int h = blockIdx.y;
    const int t = blockIdx.x * 256 + threadIdx.x;
    const fp16* base = E + (size_t)h * SEQ * SEQ + t;
    float z0 = 0.f, z1 = 0.f, z2 = 0.f, z3 = 0.f;
    for (int s = 0; s < SEQ; s += 4) {
        z0 += __half2float(base[(size_t)(s + 0) * SEQ]);
        z1 += __half2float(base[(size_t)(s + 1) * SEQ]);
        z2 += __half2float(base[(size_t)(s + 2) * SEQ]);
        z3 += __half2float(base[(size_t)(s + 3) * SEQ]);
    }
    Z[h * SEQ + t] = (z0 + z1) + (z2 + z3);
}

// ------------------------- vT transpose with 1/Z fold: vT[h][n][t] = v[t][h*128+n] / Z[h][t] ----
__global__ void __launch_bounds__(256)
transpose_scale_kernel(const fp16* __restrict__ in, fp16* __restrict__ o,
                       const float* __restrict__ Z,
                       long ibatch, int istride, long obatch, int ostride)
{
    __shared__ fp16 tile[32][34];
    const int z = blockIdx.z;
    in += (long)z * ibatch;
    o  += (long)z * obatch;
    const int c0 = blockIdx.x * 32;
    const int r0 = blockIdx.y * 32;
    const int tx = threadIdx.x & 31;
    const int ty = threadIdx.x >> 5;
#pragma unroll
    for (int j = 0; j < 4; j++)
        tile[ty + 8 * j][tx] = in[(long)(r0 + ty + 8 * j) * istride + c0 + tx];
    __syncthreads();
    const float rz = 1.0f / Z[(long)z * SEQ + r0 + tx];   // t = r0+tx, constant per thread
#pragma unroll
    for (int j = 0; j < 4; j++)
        o[(long)(c0 + ty + 8 * j) * ostride + r0 + tx] =
            __float2half(__half2float(tile[tx][ty + 8 * j]) * rz);
}

// ------------------------- launch -------------------------
extern "C" void kernel_launch(void* const* d_in, const int* in_sizes, int n_in,
                              void* d_out, int out_size)
{
    const float* query = (const float*)d_in[0];
    const float* key_  = (const float*)d_in[1];
    const float* value = (const float*)d_in[2];
    const float* Wq    = (const float*)d_in[3];
    const float* bq    = (const float*)d_in[4];
    const float* Wk    = (const float*)d_in[5];
    const float* bk    = (const float*)d_in[6];
    const float* Wv    = (const float*)d_in[7];
    const float* bv    = (const float*)d_in[8];
    const float* Wo    = (const float*)d_in[9];
    const float* bo    = (const float*)d_in[10];
    float* out = (float*)d_out;

    fp16 *in16, *wT, *woT, *qkv, *vT, *E, *cc;
    float *bias, *Z;
    cudaGetSymbolAddress((void**)&in16, g_in16);
    cudaGetSymbolAddress((void**)&wT,   g_wT);
    cudaGetSymbolAddress((void**)&woT,  g_woT);
    cudaGetSymbolAddress((void**)&bias, g_bias);
    cudaGetSymbolAddress((void**)&qkv,  g_qkv);
    cudaGetSymbolAddress((void**)&vT,   g_vT);
    cudaGetSymbolAddress((void**)&E,    g_E);
    cudaGetSymbolAddress((void**)&Z,    g_Z);
    cudaGetSymbolAddress((void**)&cc,   g_cc);

    cudaFuncSetAttribute(mma_gemm<0>, cudaFuncAttributeMaxDynamicSharedMemorySize, GSMEM);
    cudaFuncSetAttribute(mma_gemm<1>, cudaFuncAttributeMaxDynamicSharedMemorySize, GSMEM);
    cudaFuncSetAttribute(mma_gemm<2>, cudaFuncAttributeMaxDynamicSharedMemorySize, GSMEM);
    cudaFuncSetAttribute(mma_gemm<3>, cudaFuncAttributeMaxDynamicSharedMemorySize, GSMEM);

    const float inv_sqrt_dk = 0.088388347648318447f;  // 1/sqrt(128)
    const long PLANE = (long)SEQ * DMODEL;
    const long WPLANE = (long)NHEADS * DKH * DMODEL;

    // 0) inputs -> fp16 planes
    {
        const int n8 = SEQ * DMODEL / 8;
        cvt_kernel<<<n8 / 256, 256>>>((const float4*)query, (uint4*)(in16 + 0 * PLANE), n8);
        cvt_kernel<<<n8 / 256, 256>>>((const float4*)key_,  (uint4*)(in16 + 1 * PLANE), n8);
        cvt_kernel<<<n8 / 256, 256>>>((const float4*)value, (uint4*)(in16 + 2 * PLANE), n8);
    }
    // 0b) transpose+cvt weights: Wx [h][d][n] -> [i][h][n][d];  Wo [k][n] -> [n][k]
    {
        dim3 g(DKH / 32, DMODEL / 32, NHEADS);
        transpose_cvt_kernel<<<g, 256>>>(Wq, wT + 0 * WPLANE, (long)DMODEL * DKH, DKH, (long)DKH * DMODEL, DMODEL);
        transpose_cvt_kernel<<<g, 256>>>(Wk, wT + 1 * WPLANE, (long)DMODEL * DKH, DKH, (long)DKH * DMODEL, DMODEL);
        transpose_cvt_kernel<<<g, 256>>>(Wv, wT + 2 * WPLANE, (long)DMODEL * DKH, DKH, (long)DKH * DMODEL, DMODEL);
        dim3 go(DMODEL / 32, DMODEL / 32, 1);
        transpose_cvt_kernel<<<go, 256>>>(Wo, woT, 0L, DMODEL, 0L, DMODEL);
    }
    // 0c) pack biases into one buffer
    cudaMemcpyAsync(bias + 0 * DMODEL, bq, DMODEL * sizeof(float), cudaMemcpyDeviceToDevice);
    cudaMemcpyAsync(bias + 1 * DMODEL, bk, DMODEL * sizeof(float), cudaMemcpyDeviceToDevice);
    cudaMemcpyAsync(bias + 2 * DMODEL, bv, DMODEL * sizeof(float), cudaMemcpyDeviceToDevice);

    // 1) merged projections: z = i*16 + h, grid (1, 32, 48)
    {
        dim3 g(1, SEQ / BM, 48);
        mma_gemm<2><<<g, 128, GSMEM>>>(in16, wT, bias, nullptr, qkv,
                                       DMODEL, DMODEL, PLANE, DMODEL, (long)DKH * DMODEL,
                                       DMODEL, PLANE, 0L, 1.0f, 1);
    }

    // 2) E[h][s][t] = exp(q_h[s,:].k_h[t,:] / sqrt(dk))  -> fp16
    {
        dim3 g(SEQ / BN, SEQ / BM, NHEADS);
        mma_gemm<3><<<g, 128, GSMEM>>>(qkv + 0 * PLANE, qkv + 1 * PLANE, bias /*unused*/, nullptr, E,
                                       DKH, DMODEL, 128L, DMODEL, 128L,
                                       SEQ, (long)SEQ * SEQ, 0L, inv_sqrt_dk, 0);
    }

    // 3) Z[h][t] = sum_s E[h][s][t]
    {
        dim3 g(SEQ / 256, NHEADS);
        colsum_kernel<<<g, 256>>>(E, Z);
    }

    // 4) vT[h][n][t] = v[t][h*128+n] / Z[h][t]
    {
        dim3 g(DKH / 32, SEQ / 32, NHEADS);
        transpose_scale_kernel<<<g, 256>>>(qkv + 2 * PLANE, vT, Z,
                                           (long)DKH, DMODEL, (long)DKH * SEQ, SEQ);
    }

    // 5) concat[s][h*128+n] = sum_t E[h][s][t] * vT[h][n][t]  -> fp16
    {
        dim3 g(1, SEQ / BM, NHEADS);
        mma_gemm<1><<<g, 128, GSMEM>>>(E, vT, bias /*unused*/, nullptr, cc,
                                       SEQ, SEQ, (long)SEQ * SEQ, SEQ, (long)DKH * SEQ,
                                       DMODEL, 128L, 0L, 1.0f, 0);
    }

    // 6) out = concat @ Wo + bo  (fp32)
    {
        dim3 g(DMODEL / BN, SEQ / BM, 1);
        mma_gemm<0><<<g, 128, GSMEM>>>(cc, woT, bo, out, nullptr,
                                       DMODEL, DMODEL, 0L, DMODEL, 0L,
                                       DMODEL, 0L, 0L, 1.0f, 1);
    }
}

// round 11
// speedup vs baseline: 4.7898x; 1.1949x over previous
#include <cuda_runtime.h>
#include <cuda_fp16.h>
#include <math.h>

#define SEQ    2048
#define DMODEL 2048
#define NHEADS 16
#define DKH    128
typedef __half fp16;

// ------------------------- scratch (device globals) -------------------------
__device__ fp16 g_in16[3 * SEQ * DMODEL];                 // [i][s][d]  (qry, key, val fp16)
__device__ fp16 g_wT[3 * NHEADS * DKH * DMODEL];          // [i][h][n][d]
__device__ fp16 g_woT[DMODEL * DMODEL];                   // [n][k]
__device__ float g_bias[3 * DMODEL];                      // [i][h*128+n]
__device__ fp16 g_qkv[3 * SEQ * DMODEL];                  // [i][s][h*128+n]
__device__ fp16 g_vT[NHEADS * DKH * SEQ];                 // [h][n][t]  (pre-scaled by 1/Z)
__device__ fp16 g_E[(size_t)NHEADS * SEQ * SEQ];          // fp16 E=exp(scores) [h][s][t]
__device__ float g_Z[NHEADS * SEQ];                       // column sums [h][t]
__device__ fp16 g_cc[SEQ * DMODEL];                       // [s][h*128+n]

// ------------------------- helpers -------------------------
__device__ __forceinline__ unsigned smem_u32(const void* p) {
    unsigned a;
    asm("{ .reg .u64 t; cvta.to.shared.u64 t, %1; cvt.u32.u64 %0, t; }" : "=r"(a) : "l"(p));
    return a;
}
// SW128 for 128-byte rows (8 x 16B granules): granule idx ^= row & 7
__device__ __forceinline__ unsigned swz(unsigned o) {
    return o ^ (((o >> 7) & 7u) << 4);
}
__device__ __forceinline__ void ldsm4(unsigned* r, unsigned addr) {
    asm volatile("ldmatrix.sync.aligned.m8n8.x4.shared.b16 {%0,%1,%2,%3}, [%4];"
        : "=r"(r[0]), "=r"(r[1]), "=r"(r[2]), "=r"(r[3]) : "r"(addr));
}
__device__ __forceinline__ void mma16816(float* d, const unsigned* a, unsigned b0, unsigned b1) {
    asm volatile("mma.sync.aligned.m16n8k16.row.col.f32.f16.f16.f32 "
        "{%0,%1,%2,%3}, {%4,%5,%6,%7}, {%8,%9}, {%0,%1,%2,%3};"
        : "+f"(d[0]), "+f"(d[1]), "+f"(d[2]), "+f"(d[3])
        : "r"(a[0]), "r"(a[1]), "r"(a[2]), "r"(a[3]), "r"(b0), "r"(b1));
}
__device__ __forceinline__ void cp16(unsigned dst, const void* src) {
    asm volatile("cp.async.cg.shared.global [%0], [%1], 16;" :: "r"(dst), "l"(src));
}
#define CP_COMMIT() asm volatile("cp.async.commit_group;" ::: "memory")
#define CP_WAIT(n)  asm volatile("cp.async.wait_group %0;" :: "n"(n) : "memory")

__device__ __forceinline__ unsigned pack_h2(float lo, float hi) {
    half2 h = __float22half2_rn(make_float2(lo, hi));
    return *(unsigned*)&h;
}

// FMA-only exp (no MUFU pressure)
__device__ __forceinline__ float fexp(float x) {
    float t = x * 1.4426950408889634f;
    t = fmaxf(t, -125.0f);
    const float k = rintf(t);
    const float f = t - k;
    float p = 1.3333558146e-3f;
    p = fmaf(p, f, 9.6181291076e-3f);
    p = fmaf(p, f, 5.5504108664e-2f);
    p = fmaf(p, f, 2.4022650696e-1f);
    p = fmaf(p, f, 6.9314718056e-1f);
    p = fmaf(p, f, 1.0f);
    return p * __int_as_float(((int)k + 127) << 23);
}

// ------------------------- fp16 warp-MMA GEMM -------------------------
// C[z][m,n] = scale * sum_k A[z][m,k]*B[z][n,k] (+ bias[z][n])
// Block tile 64(M) x 128(N), K-chunk 64, 128 threads (4 warps, 2x2 of 32x64), occ 4.
// MODE 0: fp32 C.  MODE 1: fp16 Ch.  MODE 2: merged projections (z = i*16+h), fp16 Ch.
// MODE 3: fp16 Ch = exp(scale*acc); column sums atomically added into C (= Z[h][t]).
#define BM 64
#define BN 128
#define BKC 64
#define ST_A 0
#define ST_B 8192
#define ST_STRIDE 24576
#define GSMEM 49152

template<int MODE>
__global__ void __launch_bounds__(128, 4)
mma_gemm(const fp16* __restrict__ A, const fp16* __restrict__ B,
         const float* __restrict__ bias, float* __restrict__ C, fp16* __restrict__ Ch,
         int K, int lda, long abatch, int ldb, long bbatch,
         int ldc, long cbatch, long biasbatch, float scale, int has_bias)
{
    extern __shared__ __align__(1024) char sm[];
    const unsigned sb = smem_u32(sm);
    const int tid  = threadIdx.x;
    const int lane = tid & 31;
    const int wid  = tid >> 5;
    const int wm   = wid & 1;         // 2 x 32 rows
    const int wn   = wid >> 1;        // 2 x 64 cols
    const int z    = blockIdx.z;

    long coff;
    long boff_bias;
    if (MODE == 2) {
        const int ip = z >> 4;        // input selector (q/k/v)
        const int h  = z & 15;        // head
        A += (long)ip * abatch + (long)blockIdx.y * BM * lda;
        B += (long)z * bbatch;
        coff = (long)ip * cbatch + (long)h * 128 + (long)blockIdx.y * BM * ldc;
        boff_bias = (long)z * 128;
    } else {
        A += (long)z * abatch + (long)blockIdx.y * BM * lda;
        B += (long)z * bbatch + (long)blockIdx.x * BN * ldb;
        coff = (long)z * cbatch + (long)blockIdx.y * BM * ldc + (long)blockIdx.x * BN;
        boff_bias = (long)z * biasbatch + (long)blockIdx.x * BN;
    }

    float acc[2][8][4];
#pragma unroll
    for (int mt = 0; mt < 2; mt++)
#pragma unroll
        for (int nt = 0; nt < 8; nt++)
#pragma unroll
            for (int i = 0; i < 4; i++) acc[mt][nt][i] = 0.0f;

    // cp.async coords: granule = 16B = 8 fp16. rows r0 + 16i, granule g.
    const int r0 = tid >> 3;          // 0..15
    const int g  = tid & 7;           // 0..7
    const unsigned dbase = swz((unsigned)(r0 * 128 + g * 16));
    const long sa = (long)r0 * lda + g * 8;
    const long sbk = (long)r0 * ldb + g * 8;

    // ldmatrix coords (row-constant swizzle folded in)
    const int hi = lane >> 4;         // 0/1 -> +8 cols
    const int arow[2] = { wm * 32 + (lane & 15), wm * 32 + 16 + (lane & 15) };
    const int brow[4] = { wn * 64 + (lane & 15),      wn * 64 + 16 + (lane & 15),
                          wn * 64 + 32 + (lane & 15), wn * 64 + 48 + (lane & 15) };

    const int nch = K >> 6;

#define LOAD_CHUNK(st, k0) do {                                                     \
    const unsigned b_ = sb + (st) * ST_STRIDE;                                      \
    _Pragma("unroll")                                                               \
    for (int i = 0; i < 4; i++)                                                     \
        cp16(b_ + ST_A + dbase + i * 2048, A + sa + (long)i * 16 * lda + (k0));     \
    _Pragma("unroll")                                                               \
    for (int i = 0; i < 8; i++)                                                     \
        cp16(b_ + ST_B + dbase + i * 2048, B + sbk + (long)i * 16 * ldb + (k0));    \
} while (0)

    LOAD_CHUNK(0, 0);
    CP_COMMIT();

    for (int ch = 0; ch < nch; ch++) {
        if (ch + 1 < nch) {
            LOAD_CHUNK((ch + 1) & 1, (ch + 1) * BKC);
            CP_COMMIT();
            CP_WAIT(1);
        } else {
            CP_WAIT(0);
        }
        __syncthreads();

        const unsigned stb = sb + (ch & 1) * ST_STRIDE;
#pragma unroll
        for (int kk = 0; kk < 4; kk++) {
            const int cg = kk * 2 + hi;   // granule column 0..7
            unsigned a[2][4];
#pragma unroll
            for (int mt = 0; mt < 2; mt++) {
                const unsigned off = (unsigned)(arow[mt] * 128 + ((cg ^ (arow[mt] & 7)) * 16));
                ldsm4(a[mt], stb + ST_A + off);
            }
#pragma unroll
            for (int g4 = 0; g4 < 4; g4++) {
                const unsigned off = (unsigned)(brow[g4] * 128 + ((cg ^ (brow[g4] & 7)) * 16));
                unsigned bh[4];
                ldsm4(bh, stb + ST_B + off);
#pragma unroll
                for (int mt = 0; mt < 2; mt++) {
                    mma16816(acc[mt][2*g4],   a[mt], bh[0], bh[2]);
                    mma16816(acc[mt][2*g4+1], a[mt], bh[1], bh[3]);
                }
            }
        }
        __syncthreads();
    }
#undef LOAD_CHUNK

    // ---------------- epilogue ----------------
    const float* bz = bias + boff_bias;
    float csum[8][2];
    if (MODE == 3) {
#pragma unroll
        for (int nt = 0; nt < 8; nt++) { csum[nt][0] = 0.f; csum[nt][1] = 0.f; }
    }
#pragma unroll
    for (int mt = 0; mt < 2; mt++) {
        const int row = wm * 32 + mt * 16 + (lane >> 2);
#pragma unroll
        for (int nt = 0; nt < 8; nt++) {
            const int col = wn * 64 + nt * 8 + (lane & 3) * 2;
            float b0 = 0.f, b1 = 0.f;
            if (has_bias) { b0 = bz[col]; b1 = bz[col + 1]; }
            float x0 = fmaf(acc[mt][nt][0], scale, b0);
            float x1 = fmaf(acc[mt][nt][1], scale, b1);
            float x2 = fmaf(acc[mt][nt][2], scale, b0);
            float x3 = fmaf(acc[mt][nt][3], scale, b1);
            if (MODE == 3) {
                x0 = fexp(x0); x1 = fexp(x1); x2 = fexp(x2); x3 = fexp(x3);
                csum[nt][0] += x0 + x2;
                csum[nt][1] += x1 + x3;
            }
            if (MODE == 0) {
                float2 v01; v01.x = x0; v01.y = x1;
                float2 v23; v23.x = x2; v23.y = x3;
                *(float2*)(C + coff + (long)row * ldc + col)       = v01;
                *(float2*)(C + coff + (long)(row + 8) * ldc + col) = v23;
            } else {
                *(unsigned*)(Ch + coff + (long)row * ldc + col)       = pack_h2(x0, x1);
                *(unsigned*)(Ch + coff + (long)(row + 8) * ldc + col) = pack_h2(x2, x3);
            }
        }
    }
    if (MODE == 3) {
        // reduce column partials over the 8-lane row group, then atomic into Z (= C)
        float* Zp = C + (long)z * SEQ + (long)blockIdx.x * BN;
#pragma unroll
        for (int nt = 0; nt < 8; nt++) {
#pragma unroll
            for (int j = 0; j < 2; j++) {
                float v = csum[nt][j];
                v += __shfl_xor_sync(0xffffffffu, v, 4);
                v += __shfl_xor_sync(0xffffffffu, v, 8);
                v += __shfl_xor_sync(0xffffffffu, v, 16);
                if ((lane >> 2) == 0)
                    atomicAdd(Zp + wn * 64 + nt * 8 + (lane & 3) * 2 + j, v);
            }
        }
    }
}

// ------------------------- fp32 -> fp16: 3 tensors in one launch -------------------------
__global__ void __launch_bounds__(256)
cvt3_kernel(const float4* __restrict__ q, const float4* __restrict__ k,
            const float4* __restrict__ v, uint4* __restrict__ o, int n8)
{
    const int i = blockIdx.x * 256 + threadIdx.x;
    if (i >= n8) return;
    const int sel = blockIdx.y;
    const float4* in = (sel == 0) ? q : (sel == 1) ? k : v;
    float4 x0 = in[2*i], x1 = in[2*i + 1];
    uint4 r;
    r.x = pack_h2(x0.x, x0.y);
    r.y = pack_h2(x0.z, x0.w);
    r.z = pack_h2(x1.x, x1.y);
    r.w = pack_h2(x1.z, x1.w);
    o[(long)sel * n8 + i] = r;
}

// ------------------------- transpose+cvt 3 weight tensors in one launch -------------------------
// z = i*16+h. in: Wx[h] is [DMODEL][DKH]; out: wT[i][h] = [DKH][DMODEL].
__global__ void __launch_bounds__(256)
transpose_cvt3_kernel(const float* __restrict__ Wq, const float* __restrict__ Wk,
                      const float* __restrict__ Wv, fp16* __restrict__ o)
{
    __shared__ float tile[32][33];
    const int z = blockIdx.z;
    const int ip = z >> 4;
    const int h  = z & 15;
    const float* in = ((ip == 0) ? Wq : (ip == 1) ? Wk : Wv) + (long)h * DMODEL * DKH;
    fp16* op = o + (long)z * DKH * DMODEL;
    const int c0 = blockIdx.x * 32;
    const int r0 = blockIdx.y * 32;
    const int tx = threadIdx.x & 31;
    const int ty = threadIdx.x >> 5;
#pragma unroll
    for (int j = 0; j < 4; j++)
        tile[ty + 8 * j][tx] = in[(long)(r0 + ty + 8 * j) * DKH + c0 + tx];
    __syncthreads();
#pragma unroll
    for (int j = 0; j < 4; j++)
        op[(long)(c0 + ty + 8 * j) * DMODEL + r0 + tx] = __float2half(tile[tx][ty + 8 * j]);
}

// ------------------------- transpose + cvt (single, for Wo) -------------------------
__global__ void __launch_bounds__(256)
transpose_cvt_kernel(const float* __restrict__ in, fp16* __restrict__ o,
                     long ibatch, int istride, long obatch, int ostride)
{
    __shared__ float tile[32][33];
    const int z = blockIdx.z;
    in += (long)z * ibatch;
    o  += (long)z * obatch;
    const int c0 = blockIdx.x * 32;
    const int r0 = blockIdx.y * 32;
    const int tx = threadIdx.x & 31;
    const int ty = threadIdx.x >> 5;
#pragma unroll
    for (int j = 0; j < 4; j++)
        tile[ty + 8 * j][tx] = in[(long)(r0 + ty + 8 * j) * istride + c0 + tx];
    __syncthreads();
#pragma unroll
    for (int j = 0; j < 4; j++)
        o[(long)(c0 + ty + 8 * j) * ostride + r0 + tx] = __float2half(tile[tx][ty + 8 * j]);
}

// ------------------------- vT transpose with 1/Z fold: vT[h][n][t] = v[t][h*128+n] / Z[h][t] ----
__global__ void __launch_bounds__(256)
transpose_scale_kernel(const fp16* __restrict__ in, fp16* __restrict__ o,
                       const float* __restrict__ Z,
                       long ibatch, int istride, long obatch, int ostride)
{
    __shared__ fp16 tile[32][34];
    const int z = blockIdx.z;
    in += (long)z * ibatch;
    o  += (long)z * obatch;
    const int c0 = blockIdx.x * 32;
    const int r0 = blockIdx.y * 32;
    const int tx = threadIdx.x & 31;
    const int ty = threadIdx.x >> 5;
#pragma unroll
    for (int j = 0; j < 4; j++)
        tile[ty + 8 * j][tx] = in[(long)(r0 + ty + 8 * j) * istride + c0 + tx];
    __syncthreads();
    const float rz = 1.0f / Z[(long)z * SEQ + r0 + tx];   // t = r0+tx, constant per thread
#pragma unroll
    for (int j = 0; j < 4; j++)
        o[(long)(c0 + ty + 8 * j) * ostride + r0 + tx] =
            __float2half(__half2float(tile[tx][ty + 8 * j]) * rz);
}

// ------------------------- launch -------------------------
extern "C" void kernel_launch(void* const* d_in, const int* in_sizes, int n_in,
                              void* d_out, int out_size)
{
    const float* query = (const float*)d_in[0];
    const float* key_  = (const float*)d_in[1];
    const float* value = (const float*)d_in[2];
    const float* Wq    = (const float*)d_in[3];
    const float* bq    = (const float*)d_in[4];
    const float* Wk    = (const float*)d_in[5];
    const float* bk    = (const float*)d_in[6];
    const float* Wv    = (const float*)d_in[7];
    const float* bv    = (const float*)d_in[8];
    const float* Wo    = (const float*)d_in[9];
    const float* bo    = (const float*)d_in[10];
    float* out = (float*)d_out;

    fp16 *in16, *wT, *woT, *qkv, *vT, *E, *cc;
    float *bias, *Z;
    cudaGetSymbolAddress((void**)&in16, g_in16);
    cudaGetSymbolAddress((void**)&wT,   g_wT);
    cudaGetSymbolAddress((void**)&woT,  g_woT);
    cudaGetSymbolAddress((void**)&bias, g_bias);
    cudaGetSymbolAddress((void**)&qkv,  g_qkv);
    cudaGetSymbolAddress((void**)&vT,   g_vT);
    cudaGetSymbolAddress((void**)&E,    g_E);
    cudaGetSymbolAddress((void**)&Z,    g_Z);
    cudaGetSymbolAddress((void**)&cc,   g_cc);

    cudaFuncSetAttribute(mma_gemm<0>, cudaFuncAttributeMaxDynamicSharedMemorySize, GSMEM);
    cudaFuncSetAttribute(mma_gemm<1>, cudaFuncAttributeMaxDynamicSharedMemorySize, GSMEM);
    cudaFuncSetAttribute(mma_gemm<2>, cudaFuncAttributeMaxDynamicSharedMemorySize, GSMEM);
    cudaFuncSetAttribute(mma_gemm<3>, cudaFuncAttributeMaxDynamicSharedMemorySize, GSMEM);

    const float inv_sqrt_dk = 0.088388347648318447f;  // 1/sqrt(128)
    const long PLANE = (long)SEQ * DMODEL;

    // 0) inputs -> fp16 planes (one launch), Z zeroed
    {
        const int n8 = SEQ * DMODEL / 8;
        dim3 g(n8 / 256, 3);
        cvt3_kernel<<<g, 256>>>((const float4*)query, (const float4*)key_,
                                (const float4*)value, (uint4*)in16, n8);
    }
    cudaMemsetAsync(Z, 0, NHEADS * SEQ * sizeof(float));
    // 0b) transpose+cvt all projection weights (one launch), Wo separately
    {
        dim3 g(DKH / 32, DMODEL / 32, 48);
        transpose_cvt3_kernel<<<g, 256>>>(Wq, Wk, Wv, wT);
        dim3 go(DMODEL / 32, DMODEL / 32, 1);
        transpose_cvt_kernel<<<go, 256>>>(Wo, woT, 0L, DMODEL, 0L, DMODEL);
    }
    // 0c) pack biases into one buffer
    cudaMemcpyAsync(bias + 0 * DMODEL, bq, DMODEL * sizeof(float), cudaMemcpyDeviceToDevice);
    cudaMemcpyAsync(bias + 1 * DMODEL, bk, DMODEL * sizeof(float), cudaMemcpyDeviceToDevice);
    cudaMemcpyAsync(bias + 2 * DMODEL, bv, DMODEL * sizeof(float), cudaMemcpyDeviceToDevice);

    // 1) merged projections: z = i*16 + h, grid (1, 32, 48)
    {
        dim3 g(1, SEQ / BM, 48);
        mma_gemm<2><<<g, 128, GSMEM>>>(in16, wT, bias, nullptr, qkv,
                                       DMODEL, DMODEL, PLANE, DMODEL, (long)DKH * DMODEL,
                                       DMODEL, PLANE, 0L, 1.0f, 1);
    }

    // 2) E[h][s][t] = exp(q_h[s,:].k_h[t,:] / sqrt(dk)) -> fp16; Z[h][t] += column sums
    {
        dim3 g(SEQ / BN, SEQ / BM, NHEADS);
        mma_gemm<3><<<g, 128, GSMEM>>>(qkv + 0 * PLANE, qkv + 1 * PLANE, bias /*unused*/, Z, E,
                                       DKH, DMODEL, 128L, DMODEL, 128L,
                                       SEQ, (long)SEQ * SEQ, 0L, inv_sqrt_dk, 0);
    }

    // 3) vT[h][n][t] = v[t][h*128+n] / Z[h][t]
    {
        dim3 g(DKH / 32, SEQ / 32, NHEADS);
        transpose_scale_kernel<<<g, 256>>>(qkv + 2 * PLANE, vT, Z,
                                           (long)DKH, DMODEL, (long)DKH * SEQ, SEQ);
    }

    // 4) concat[s][h*128+n] = sum_t E[h][s][t] * vT[h][n][t]  -> fp16
    {
        dim3 g(1, SEQ / BM, NHEADS);
        mma_gemm<1><<<g, 128, GSMEM>>>(E, vT, bias /*unused*/, nullptr, cc,
                                       SEQ, SEQ, (long)SEQ * SEQ, SEQ, (long)DKH * SEQ,
                                       DMODEL, 128L, 0L, 1.0f, 0);
    }

    // 5) out = concat @ Wo + bo  (fp32)
    {
        dim3 g(DMODEL / BN, SEQ / BM, 1);
        mma_gemm<0><<<g, 128, GSMEM>>>(cc, woT, bo, out, nullptr,
                                       DMODEL, DMODEL, 0L, DMODEL, 0L,
                                       DMODEL, 0L, 0L, 1.0f, 1);
    }
}